// round 9
// baseline (speedup 1.0000x reference)
#include <cuda_runtime.h>
#include <cuda_bf16.h>
#include <cstdint>
#include <math.h>

// ---------------- problem-size constants (from reference) ----------------
#define NMAXN 100000
#define EMAXE 1600000
#define BMAXB 4096
#define LP1   51

#define EPSF 1e-7f
#define MINN 1e-15f
#define MAXN 1e6f

// ---------------- device scratch (static: no allocations allowed) --------
__device__ float g_scale[NMAXN];
__device__ float g_TA[NMAXN * 128];
__device__ float g_T1[NMAXN * 128];
__device__ float g_TM[NMAXN * 128];
__device__ float g_T2[NMAXN * 128];
__device__ float g_X2[NMAXN * 128];
__device__ float g_G [BMAXB * LP1 * 128];
__device__ float g_H [BMAXB * LP1 * 64];
__device__ float g_ub[3][128];
__device__ float g_cp[3];        // c, K=1/c, sqrtK
__device__ float g_loss;
// CSR scratch
__device__ int   g_cnt[NMAXN];
__device__ int   g_off[NMAXN + 1];
__device__ int   g_cur[NMAXN];
__device__ int   g_ccol[EMAXE];
__device__ float g_cval[EMAXE];
__device__ int   g_bsum[512];

// ---------------- small device helpers ----------------
__device__ __forceinline__ float wsum(float v) {
#pragma unroll
    for (int o = 16; o; o >>= 1) v += __shfl_xor_sync(0xffffffffu, v, o);
    return v;
}

__device__ __forceinline__ float f_arcosh(float x) {
    x = fmaxf(x, 1.0f + EPSF);
    return logf(x + sqrtf(x * x - 1.0f));
}

// exp0log0: logmap0(proj(expmap0(u))) with the reference's clamps.
__device__ __forceinline__ void d_EL(float* u, float sqrtK, float Kc) {
    float sq = wsum(u[0]*u[0] + u[1]*u[1] + u[2]*u[2] + u[3]*u[3]);
    float xn = fmaxf(sqrtf(sq), MINN);
    float th = xn / sqrtK;
    float coef = sqrtK * sinhf(th) / xn;
    u[0] *= coef; u[1] *= coef; u[2] *= coef; u[3] *= coef;
    float rs = wsum(u[0]*u[0] + u[1]*u[1] + u[2]*u[2] + u[3]*u[3]);
    float x0 = sqrtf(Kc + rs);
    float yn = fmaxf(sqrtf(rs), MINN);
    float s = sqrtK * f_arcosh(x0 / sqrtK);
    float f = s / yn;
    u[0] *= f; u[1] *= f; u[2] *= f; u[3] *= f;
}

// tangent u -> expmap0 -> mobius_add(point, bias) -> logmap0 -> tangent (in place)
__device__ __forceinline__ void d_TBT(float* u, const float* ub, float sqrtK,
                                      float Kc, int lane) {
    float sq = wsum(u[0]*u[0] + u[1]*u[1] + u[2]*u[2] + u[3]*u[3]);
    float xn = fmaxf(sqrtf(sq), MINN);
    float th = xn / sqrtK;
    float coef = sqrtK * sinhf(th) / xn;
    float a0 = coef*u[0], a1 = coef*u[1], a2 = coef*u[2], a3 = coef*u[3];
    float sp2 = wsum(a0*a0 + a1*a1 + a2*a2 + a3*a3);
    float x0 = sqrtf(Kc + sp2);
    float yn = fmaxf(sqrtf(sp2), MINN);
    float y0 = a0/yn, y1 = a1/yn, y2 = a2/yn, y3 = a3/yn;
    float ub0 = ub[lane*4+0], ub1 = ub[lane*4+1], ub2 = ub[lane*4+2], ub3 = ub[lane*4+3];
    float alpha = wsum(y0*ub0 + y1*ub1 + y2*ub2 + y3*ub3) / sqrtK;
    float c2 = alpha * (sqrtK - x0);
    float w0 = ub0 - c2*y0, w1 = ub1 - c2*y1, w2 = ub2 - c2*y2, w3 = ub3 - c2*y3;
    float wt = wsum(a0*w0 + a1*w1 + a2*w2 + a3*w3) / fmaxf(x0, EPSF);
    float md = wsum(w0*w0 + w1*w1 + w2*w2 + w3*w3) - wt*wt;
    float normu = sqrtf(fmaxf(md, EPSF));
    normu = fminf(normu, MAXN);
    float th2 = fmaxf(normu / sqrtK, MINN);
    float ch = coshf(th2);
    float sh = sinhf(th2) / th2;
    float r0 = ch*a0 + sh*w0, r1 = ch*a1 + sh*w1, r2 = ch*a2 + sh*w2, r3 = ch*a3 + sh*w3;
    float rs2 = wsum(r0*r0 + r1*r1 + r2*r2 + r3*r3);
    float x0n = sqrtf(Kc + rs2);
    float yn2 = fmaxf(sqrtf(rs2), MINN);
    float s = sqrtK * f_arcosh(x0n / sqrtK);
    float f = s / yn2;
    u[0] = f*r0; u[1] = f*r1; u[2] = f*r2; u[3] = f*r3;
}

// ---------------- elementwise / graph kernels ----------------

__global__ void k_init(const float* __restrict__ rawc,
                       const float* __restrict__ b0,
                       const float* __restrict__ b1,
                       const float* __restrict__ b2) {
    int lane = threadIdx.x;
    float rc = rawc[0];
    float c = fmaxf(rc, 0.f) + log1pf(expf(-fabsf(rc))) + 1e-5f;
    float Kc = 1.f / c;
    float sqrtK = sqrtf(Kc);
    if (lane == 0) { g_cp[0] = c; g_cp[1] = Kc; g_cp[2] = sqrtK; g_loss = 0.f; }
    const float* bs[3] = {b0, b1, b2};
#pragma unroll
    for (int k = 0; k < 3; k++) {
        float u[4];
#pragma unroll
        for (int i = 0; i < 4; i++) u[i] = bs[k][lane*4 + i];
        if (lane == 0) u[0] = 0.f;
        d_EL(u, sqrtK, Kc);
#pragma unroll
        for (int i = 0; i < 4; i++) g_ub[k][lane*4 + i] = u[i];
    }
}

__global__ void k_scale(const float* __restrict__ A1, int N) {
    int w = (blockIdx.x * blockDim.x + threadIdx.x) >> 5;
    if (w >= N) return;
    int lane = threadIdx.x & 31;
    float sqrtK = g_cp[2];
    const float4 v = *((const float4*)(A1 + (size_t)w * 128) + lane);
    float s4 = v.x*v.x + v.y*v.y + v.z*v.z + v.w*v.w;
    if (lane == 0) s4 -= v.x*v.x;
    float sq = wsum(s4);
    if (lane == 0) {
        float yn = fmaxf(sqrtf(sq), MINN);
        float s = sqrtK * f_arcosh(__ldg(A1 + (size_t)w * 128) / sqrtK);
        g_scale[w] = s / yn;
    }
}

__global__ void k_zero(float* __restrict__ p, int n) {
    int i = blockIdx.x * blockDim.x + threadIdx.x;
    int st = gridDim.x * blockDim.x;
    for (; i < n; i += st) p[i] = 0.f;
}

// ---------------- CSR build ----------------
__global__ void k_zcnt(int N) {
    int i = blockIdx.x * blockDim.x + threadIdx.x;
    if (i < N) g_cnt[i] = 0;
}
__global__ void k_hist(const int* __restrict__ rows, int E) {
    int e = blockIdx.x * blockDim.x + threadIdx.x;
    if (e < E) atomicAdd(&g_cnt[__ldg(rows + e)], 1);
}
__global__ void k_scan1(int N) {
    __shared__ int sh[256];
    int b = blockIdx.x, t = threadIdx.x;
    int idx = b * 256 + t;
    int v = (idx < N) ? g_cnt[idx] : 0;
    sh[t] = v;
    __syncthreads();
    for (int o = 1; o < 256; o <<= 1) {
        int x = (t >= o) ? sh[t - o] : 0;
        __syncthreads();
        sh[t] += x;
        __syncthreads();
    }
    if (idx < N) g_off[idx] = sh[t] - v;
    if (t == 255) g_bsum[b] = sh[255];
}
__global__ void k_scan2(int nb) {
    __shared__ int sh[512];
    int t = threadIdx.x;
    int v = (t < nb) ? g_bsum[t] : 0;
    sh[t] = v;
    __syncthreads();
    for (int o = 1; o < 512; o <<= 1) {
        int x = (t >= o) ? sh[t - o] : 0;
        __syncthreads();
        sh[t] += x;
        __syncthreads();
    }
    if (t < nb) g_bsum[t] = sh[t] - v;
}
__global__ void k_scan3(int N, int E) {
    int i = blockIdx.x * blockDim.x + threadIdx.x;
    if (i < N) {
        int o = g_off[i] + g_bsum[i >> 8];
        g_off[i] = o;
        g_cur[i] = o;
    }
    if (i == 0) g_off[N] = E;
}
__global__ void k_scatter(const int* __restrict__ rows, const int* __restrict__ cols,
                          const float* __restrict__ vals, int E) {
    int e = blockIdx.x * blockDim.x + threadIdx.x;
    if (e >= E) return;
    int r = __ldg(rows + e);
    int pos = atomicAdd(&g_cur[r], 1);
    g_ccol[pos] = __ldg(cols + e);
    g_cval[pos] = __ldg(vals + e);
}

// ---------------- CSR SpMM with fused nonlinearity ---------------------------
// FUSE=1: mix chain -> OUT=TM (needs nvec + g_TA). FUSE=2: single EL -> OUT=X2.
template<int FUSE>
__global__ void k_csrmm(const float* __restrict__ T, float* __restrict__ OUT,
                        const float* __restrict__ nvec, int N) {
    int w = (blockIdx.x * blockDim.x + threadIdx.x) >> 5;
    if (w >= N) return;
    int lane = threadIdx.x & 31;
    int e0 = __ldg(g_off + w);
    int e1 = __ldg(g_off + w + 1);
    float a[4] = {0.f, 0.f, 0.f, 0.f};
    int e = e0;
    for (; e + 2 <= e1; e += 2) {
        int c0 = __ldg(g_ccol + e);
        int c1 = __ldg(g_ccol + e + 1);
        float v0 = __ldg(g_cval + e);
        float v1 = __ldg(g_cval + e + 1);
        float4 t0 = __ldg((const float4*)(T + (size_t)c0 * 128) + lane);
        float4 t1 = __ldg((const float4*)(T + (size_t)c1 * 128) + lane);
        a[0] += t0.x * v0 + t1.x * v1;
        a[1] += t0.y * v0 + t1.y * v1;
        a[2] += t0.z * v0 + t1.z * v1;
        a[3] += t0.w * v0 + t1.w * v1;
    }
    if (e < e1) {
        int c0 = __ldg(g_ccol + e);
        float v0 = __ldg(g_cval + e);
        float4 t0 = __ldg((const float4*)(T + (size_t)c0 * 128) + lane);
        a[0] += t0.x * v0; a[1] += t0.y * v0; a[2] += t0.z * v0; a[3] += t0.w * v0;
    }
    float sqrtK = g_cp[2], Kc = g_cp[1];
    if (FUSE == 1) {
        d_EL(a, sqrtK, Kc);
        float nv = __ldg(nvec + w);
        float om = 1.f - nv;
#pragma unroll
        for (int i = 0; i < 4; i++) a[i] *= om;
        d_EL(a, sqrtK, Kc);
        float b[4];
        float4 v = *((const float4*)(g_TA + (size_t)w * 128) + lane);
        b[0]=v.x*nv; b[1]=v.y*nv; b[2]=v.z*nv; b[3]=v.w*nv;
        d_EL(b, sqrtK, Kc);
#pragma unroll
        for (int i = 0; i < 4; i++) a[i] += b[i];
        d_EL(a, sqrtK, Kc);
    } else if (FUSE == 2) {
        d_EL(a, sqrtK, Kc);
    }
    *((float4*)(OUT + (size_t)w * 128) + lane) = make_float4(a[0], a[1], a[2], a[3]);
}

__global__ void k_gather(const int* __restrict__ bidx, int L) {
    int b = blockIdx.x;
    int d = threadIdx.x;
    float acc = 0.f;
    float* Gb = g_G + (size_t)b * (L + 1) * 128;
    const int* ib = bidx + (size_t)b * L;
    for (int l = 0; l < L; l++) {
        int node = __ldg(ib + l);
        float v = __ldg(g_X2 + (size_t)node * 128 + d);
        Gb[(size_t)l * 128 + d] = v;
        acc += v;
    }
    Gb[(size_t)L * 128 + d] = acc;
}

__global__ void k_addbias(float* __restrict__ o, const float* __restrict__ bias, int n) {
    int i = blockIdx.x * blockDim.x + threadIdx.x;
    if (i < n) o[i] += __ldg(bias + (i & 127));
}

__global__ void k_loss(const float* __restrict__ sel, const float* __restrict__ cls,
                       const float* __restrict__ cb, const int* __restrict__ lab, int B) {
    int b = (blockIdx.x * blockDim.x + threadIdx.x) >> 5;
    if (b >= B) return;
    int lane = threadIdx.x & 31;
    const float* row = sel + (size_t)b * 128;
    float d0 = 0.f, d1 = 0.f;
#pragma unroll
    for (int i = 0; i < 4; i++) {
        int d = lane * 4 + i;
        float o = row[d];
        d0 += o * __ldg(cls + d * 2 + 0);
        d1 += o * __ldg(cls + d * 2 + 1);
    }
    d0 = wsum(d0); d1 = wsum(d1);
    if (lane == 0) {
        float p0 = d0 + __ldg(cb + 0);
        float p1 = d1 + __ldg(cb + 1);
        float m = fmaxf(p0, p1);
        float lse = m + logf(expf(p0 - m) + expf(p1 - m));
        int y = __ldg(lab + b);
        float lp = (y == 0 ? p0 : p1) - lse;
        atomicAdd(&g_loss, lp);
    }
}

__global__ void k_final(float* __restrict__ out, int out_size, int B) {
    out[0] = -g_loss / (float)B;
    out[out_size - 1] = g_cp[0];
}

// ---------------- mma.sync helpers ----------------
__device__ __forceinline__ void ldm_x4(uint32_t* r, uint32_t addr) {
    asm volatile("ldmatrix.sync.aligned.m8n8.x4.shared.b16 {%0,%1,%2,%3}, [%4];"
        : "=r"(r[0]), "=r"(r[1]), "=r"(r[2]), "=r"(r[3]) : "r"(addr));
}
__device__ __forceinline__ void mma_bf16(float* c, const uint32_t* a, const uint32_t* b) {
    asm volatile("mma.sync.aligned.m16n8k16.row.col.f32.bf16.bf16.f32 "
        "{%0,%1,%2,%3}, {%4,%5,%6,%7}, {%8,%9}, {%0,%1,%2,%3};"
        : "+f"(c[0]), "+f"(c[1]), "+f"(c[2]), "+f"(c[3])
        : "r"(a[0]), "r"(a[1]), "r"(a[2]), "r"(a[3]), "r"(b[0]), "r"(b[1]));
}
__device__ __forceinline__ uint32_t pack_hi2(float x, float y) {
    __nv_bfloat16 hx = __float2bfloat16(x), hy = __float2bfloat16(y);
    return ((uint32_t)__bfloat16_as_ushort(hy) << 16) | __bfloat16_as_ushort(hx);
}
__device__ __forceinline__ uint32_t pack_lo2(float x, float y) {
    __nv_bfloat16 hx = __float2bfloat16(x), hy = __float2bfloat16(y);
    __nv_bfloat16 lx = __float2bfloat16(x - __bfloat162float(hx));
    __nv_bfloat16 ly = __float2bfloat16(y - __bfloat162float(hy));
    return ((uint32_t)__bfloat16_as_ushort(ly) << 16) | __bfloat16_as_ushort(lx);
}

// ---------------- fused GEMM + TBT epilogue (K=128, N=128, A resident) -------
// For each pass p: O_p = TBT( diag(scale)*A' @ B_p , ub[ubi_p] ), time slot zeroed.
// B/C share the same smem region (B dead after MMAs of the pass).
#define DLDK 136
#define FLDC 132
#define FUSED_SMEM (4 * 128 * DLDK * 2)
template<int NPASS, bool ASCALE>
__global__ void __launch_bounds__(512)
mmgemm_fused(int M, const float* __restrict__ A, const float* __restrict__ scale,
             const float* __restrict__ B0, const float* __restrict__ B1,
             float* __restrict__ O0, float* __restrict__ O1,
             int ubi0, int ubi1) {
    extern __shared__ __align__(16) char dsmc[];
    __nv_bfloat16* AsH = (__nv_bfloat16*)dsmc;
    __nv_bfloat16* AsL = AsH + 128 * DLDK;
    __nv_bfloat16* BsH = AsL + 128 * DLDK;
    __nv_bfloat16* BsL = BsH + 128 * DLDK;
    float* Cs = (float*)BsH;            // aliases B region (69.6KB >= 67.6KB)

    int tid = threadIdx.x;
    int lane = tid & 31;
    int wid = tid >> 5;
    int wm = wid >> 2;
    int wn = wid & 3;
    int m0 = blockIdx.x * 128;
    float sqrtK = g_cp[2], Kc = g_cp[1];

    // ---- A: load fp32, (scale, zero col0), split to hi/lo — once
#pragma unroll
    for (int t = 0; t < 8; t++) {
        int i = tid + t * 512;
        int r = i >> 5;
        int kc = (i & 31) * 4;
        int gr = m0 + r;
        float4 v = make_float4(0.f, 0.f, 0.f, 0.f);
        if (gr < M) {
            v = *reinterpret_cast<const float4*>(A + (size_t)gr * 128 + kc);
            if (ASCALE) {
                float s = __ldg(scale + gr);
                v.x *= s; v.y *= s; v.z *= s; v.w *= s;
                if (kc == 0) v.x = 0.f;
            }
        }
        *(uint32_t*)&AsH[r * DLDK + kc]     = pack_hi2(v.x, v.y);
        *(uint32_t*)&AsH[r * DLDK + kc + 2] = pack_hi2(v.z, v.w);
        *(uint32_t*)&AsL[r * DLDK + kc]     = pack_lo2(v.x, v.y);
        *(uint32_t*)&AsL[r * DLDK + kc + 2] = pack_lo2(v.z, v.w);
    }

    int a_row = (lane & 7) + ((lane >> 3) & 1) * 8;
    int a_kof = (lane >> 4) * 8;
    int b_row = (lane & 7) + (lane >> 4) * 8;
    int b_kof = ((lane >> 3) & 1) * 8;

    float acc[2][4][4];

#pragma unroll
    for (int pass = 0; pass < NPASS; pass++) {
        const float* Bg = pass ? B1 : B0;
        float* Og = pass ? O1 : O0;
        int ubi = pass ? ubi1 : ubi0;

        // ---- B: transpose-convert [K,N] -> Bs[n][k] hi/lo
#pragma unroll
        for (int t = 0; t < 8; t++) {
            int i = tid + t * 512;
            int kk = i >> 5;
            int nc = (i & 31) * 4;
            float4 v = *reinterpret_cast<const float4*>(Bg + (size_t)kk * 128 + nc);
            float vv[4] = {v.x, v.y, v.z, v.w};
#pragma unroll
            for (int j = 0; j < 4; j++) {
                __nv_bfloat16 h = __float2bfloat16(vv[j]);
                BsH[(nc + j) * DLDK + kk] = h;
                BsL[(nc + j) * DLDK + kk] = __float2bfloat16(vv[j] - __bfloat162float(h));
            }
        }
        __syncthreads();

#pragma unroll
        for (int i = 0; i < 2; i++)
#pragma unroll
            for (int j = 0; j < 4; j++)
#pragma unroll
                for (int q = 0; q < 4; q++) acc[i][j][q] = 0.f;

#pragma unroll
        for (int kk = 0; kk < 128; kk += 16) {
            uint32_t ah[2][4], al[2][4], bh[2][4], bl[2][4];
#pragma unroll
            for (int mt = 0; mt < 2; mt++) {
                int row = wm * 32 + mt * 16 + a_row;
                int col = kk + a_kof;
                ldm_x4(ah[mt], (uint32_t)__cvta_generic_to_shared(&AsH[row * DLDK + col]));
                ldm_x4(al[mt], (uint32_t)__cvta_generic_to_shared(&AsL[row * DLDK + col]));
            }
#pragma unroll
            for (int np = 0; np < 2; np++) {
                int nrow = wn * 32 + np * 16 + b_row;
                int col = kk + b_kof;
                ldm_x4(bh[np], (uint32_t)__cvta_generic_to_shared(&BsH[nrow * DLDK + col]));
                ldm_x4(bl[np], (uint32_t)__cvta_generic_to_shared(&BsL[nrow * DLDK + col]));
            }
#pragma unroll
            for (int np = 0; np < 2; np++)
#pragma unroll
                for (int mt = 0; mt < 2; mt++) {
                    mma_bf16(acc[mt][2*np],   ah[mt], bh[np]);
                    mma_bf16(acc[mt][2*np+1], ah[mt], bh[np] + 2);
                }
#pragma unroll
            for (int np = 0; np < 2; np++)
#pragma unroll
                for (int mt = 0; mt < 2; mt++) {
                    mma_bf16(acc[mt][2*np],   ah[mt], bl[np]);
                    mma_bf16(acc[mt][2*np+1], ah[mt], bl[np] + 2);
                }
#pragma unroll
            for (int np = 0; np < 2; np++)
#pragma unroll
                for (int mt = 0; mt < 2; mt++) {
                    mma_bf16(acc[mt][2*np],   al[mt], bh[np]);
                    mma_bf16(acc[mt][2*np+1], al[mt], bh[np] + 2);
                }
        }
        __syncthreads();                 // all MMA reads of Bs done

        // ---- stage C tile to smem (aliases B region)
#pragma unroll
        for (int mt = 0; mt < 2; mt++) {
            int row0 = wm * 32 + mt * 16 + (lane >> 2);
            int row1 = row0 + 8;
#pragma unroll
            for (int nt = 0; nt < 4; nt++) {
                int col = wn * 32 + nt * 8 + (lane & 3) * 2;
                *reinterpret_cast<float2*>(&Cs[row0 * FLDC + col]) =
                    make_float2(acc[mt][nt][0], acc[mt][nt][1]);
                *reinterpret_cast<float2*>(&Cs[row1 * FLDC + col]) =
                    make_float2(acc[mt][nt][2], acc[mt][nt][3]);
            }
        }
        __syncthreads();

        // ---- TBT epilogue: warp-per-row (16 warps x 8 rows)
        const float* ub = g_ub[ubi];
#pragma unroll
        for (int r8 = 0; r8 < 8; r8++) {
            int r = wid * 8 + r8;
            int gr = m0 + r;
            float u[4];
            u[0] = Cs[r * FLDC + lane*4 + 0];
            u[1] = Cs[r * FLDC + lane*4 + 1];
            u[2] = Cs[r * FLDC + lane*4 + 2];
            u[3] = Cs[r * FLDC + lane*4 + 3];
            if (lane == 0) u[0] = 0.f;     // proj_tan0 (expmap0 ignores time slot)
            d_TBT(u, ub, sqrtK, Kc, lane);
            if (gr < M)
                *((float4*)(Og + (size_t)gr * 128) + lane) =
                    make_float4(u[0], u[1], u[2], u[3]);
        }
        if (pass + 1 < NPASS) __syncthreads();   // before next B load overwrites Cs
    }
}

// ---------------- general mma.sync GEMM (pipelined, term-reordered) ----------
template<int BM, int BN, int BK, int NWM, int NWN, bool BT, bool RELU, bool ASCALE, bool ATOMIC>
__global__ void __launch_bounds__(NWM * NWN * 32)
mmgemm(int M, int N, int K, int kChunk,
       const float* __restrict__ A, int lda,
       const float* __restrict__ B, int ldb,
       float* __restrict__ C, int ldc,
       const float* __restrict__ scale) {
    constexpr int THREADS = NWM * NWN * 32;
    constexpr int WM = BM / NWM;
    constexpr int WN = BN / NWN;
    constexpr int MT = WM / 16;
    constexpr int NT = WN / 8;
    constexpr int NP = NT / 2;
    constexpr int LDK = BK + 8;
    constexpr int NA = (BM * (BK / 4) + THREADS - 1) / THREADS;
    constexpr int NBCNT = BT ? BN * (BK / 4) : BK * (BN / 4);
    constexpr int NB = (NBCNT + THREADS - 1) / THREADS;

    __shared__ __align__(16) __nv_bfloat16 AsH[BM * LDK];
    __shared__ __align__(16) __nv_bfloat16 AsL[BM * LDK];
    __shared__ __align__(16) __nv_bfloat16 BsH[BN * LDK];
    __shared__ __align__(16) __nv_bfloat16 BsL[BN * LDK];

    int tid = threadIdx.x;
    int lane = tid & 31;
    int wid = tid >> 5;
    int wm = wid / NWN;
    int wn = wid % NWN;
    int m0 = blockIdx.x * BM;
    int n0 = blockIdx.y * BN;
    int kStart = blockIdx.z * kChunk;
    int kEnd = min(K, kStart + kChunk);

    float acc[MT][NT][4];
#pragma unroll
    for (int i = 0; i < MT; i++)
#pragma unroll
        for (int j = 0; j < NT; j++)
#pragma unroll
            for (int q = 0; q < 4; q++) acc[i][j][q] = 0.f;

    float4 pa[NA]; float ps[NA]; float4 pb[NB];

    auto loadA = [&](int k0) {
#pragma unroll
        for (int t = 0; t < NA; t++) {
            int i = tid + t * THREADS;
            float4 v = make_float4(0.f, 0.f, 0.f, 0.f);
            float s = 0.f;
            if (i < BM * (BK / 4)) {
                int r = i / (BK / 4);
                int kc = (i % (BK / 4)) * 4;
                int gr = m0 + r;
                if (gr < M) {
                    v = *reinterpret_cast<const float4*>(A + (size_t)gr * lda + k0 + kc);
                    if (ASCALE) s = __ldg(scale + gr);
                }
            }
            pa[t] = v;
            if (ASCALE) ps[t] = s;
        }
    };
    auto storeA = [&](int k0) {
#pragma unroll
        for (int t = 0; t < NA; t++) {
            int i = tid + t * THREADS;
            if (i < BM * (BK / 4)) {
                int r = i / (BK / 4);
                int kc = (i % (BK / 4)) * 4;
                float4 v = pa[t];
                if (ASCALE) {
                    float s = ps[t];
                    v.x *= s; v.y *= s; v.z *= s; v.w *= s;
                    if (k0 + kc == 0) v.x = 0.f;
                }
                *(uint32_t*)&AsH[r * LDK + kc]     = pack_hi2(v.x, v.y);
                *(uint32_t*)&AsH[r * LDK + kc + 2] = pack_hi2(v.z, v.w);
                *(uint32_t*)&AsL[r * LDK + kc]     = pack_lo2(v.x, v.y);
                *(uint32_t*)&AsL[r * LDK + kc + 2] = pack_lo2(v.z, v.w);
            }
        }
    };
    auto loadB = [&](int k0) {
#pragma unroll
        for (int t = 0; t < NB; t++) {
            int i = tid + t * THREADS;
            float4 v = make_float4(0.f, 0.f, 0.f, 0.f);
            if (i < NBCNT) {
                if (BT) {
                    int r = i / (BK / 4);
                    int kc = (i % (BK / 4)) * 4;
                    v = *reinterpret_cast<const float4*>(B + (size_t)(n0 + r) * ldb + k0 + kc);
                } else {
                    int kk = i / (BN / 4);
                    int nc = (i % (BN / 4)) * 4;
                    v = *reinterpret_cast<const float4*>(B + (size_t)(k0 + kk) * ldb + n0 + nc);
                }
            }
            pb[t] = v;
        }
    };
    auto storeB = [&]() {
#pragma unroll
        for (int t = 0; t < NB; t++) {
            int i = tid + t * THREADS;
            if (i < NBCNT) {
                float4 v = pb[t];
                if (BT) {
                    int r = i / (BK / 4);
                    int kc = (i % (BK / 4)) * 4;
                    *(uint32_t*)&BsH[r * LDK + kc]     = pack_hi2(v.x, v.y);
                    *(uint32_t*)&BsH[r * LDK + kc + 2] = pack_hi2(v.z, v.w);
                    *(uint32_t*)&BsL[r * LDK + kc]     = pack_lo2(v.x, v.y);
                    *(uint32_t*)&BsL[r * LDK + kc + 2] = pack_lo2(v.z, v.w);
                } else {
                    int kk = i / (BN / 4);
                    int nc = (i % (BN / 4)) * 4;
                    float vv[4] = {v.x, v.y, v.z, v.w};
#pragma unroll
                    for (int j = 0; j < 4; j++) {
                        __nv_bfloat16 h = __float2bfloat16(vv[j]);
                        BsH[(nc + j) * LDK + kk] = h;
                        BsL[(nc + j) * LDK + kk] = __float2bfloat16(vv[j] - __bfloat162float(h));
                    }
                }
            }
        }
    };

    int a_row = (lane & 7) + ((lane >> 3) & 1) * 8;
    int a_kof = (lane >> 4) * 8;
    int b_row = (lane & 7) + (lane >> 4) * 8;
    int b_kof = ((lane >> 3) & 1) * 8;

    loadA(kStart);
    loadB(kStart);

    for (int k0 = kStart; k0 < kEnd; k0 += BK) {
        storeA(k0);
        storeB();
        __syncthreads();
        if (k0 + BK < kEnd) {
            loadA(k0 + BK);
            loadB(k0 + BK);
        }
#pragma unroll
        for (int kk = 0; kk < BK; kk += 16) {
            uint32_t ah[MT][4], al[MT][4], bh[NP][4], bl[NP][4];
#pragma unroll
            for (int mt = 0; mt < MT; mt++) {
                int row = wm * WM + mt * 16 + a_row;
                int col = kk + a_kof;
                ldm_x4(ah[mt], (uint32_t)__cvta_generic_to_shared(&AsH[row * LDK + col]));
                ldm_x4(al[mt], (uint32_t)__cvta_generic_to_shared(&AsL[row * LDK + col]));
            }
#pragma unroll
            for (int np = 0; np < NP; np++) {
                int nrow = wn * WN + np * 16 + b_row;
                int col = kk + b_kof;
                ldm_x4(bh[np], (uint32_t)__cvta_generic_to_shared(&BsH[nrow * LDK + col]));
                ldm_x4(bl[np], (uint32_t)__cvta_generic_to_shared(&BsL[nrow * LDK + col]));
            }
#pragma unroll
            for (int np = 0; np < NP; np++)
#pragma unroll
                for (int mt = 0; mt < MT; mt++) {
                    mma_bf16(acc[mt][2*np],   ah[mt], bh[np]);
                    mma_bf16(acc[mt][2*np+1], ah[mt], bh[np] + 2);
                }
#pragma unroll
            for (int np = 0; np < NP; np++)
#pragma unroll
                for (int mt = 0; mt < MT; mt++) {
                    mma_bf16(acc[mt][2*np],   ah[mt], bl[np]);
                    mma_bf16(acc[mt][2*np+1], ah[mt], bl[np] + 2);
                }
#pragma unroll
            for (int np = 0; np < NP; np++)
#pragma unroll
                for (int mt = 0; mt < MT; mt++) {
                    mma_bf16(acc[mt][2*np],   al[mt], bh[np]);
                    mma_bf16(acc[mt][2*np+1], al[mt], bh[np] + 2);
                }
        }
        __syncthreads();
    }

#pragma unroll
    for (int mt = 0; mt < MT; mt++) {
        int row0 = m0 + wm * WM + mt * 16 + (lane >> 2);
        int row1 = row0 + 8;
#pragma unroll
        for (int nt = 0; nt < NT; nt++) {
            int col = n0 + wn * WN + nt * 8 + (lane & 3) * 2;
            float c0 = acc[mt][nt][0], c1 = acc[mt][nt][1];
            float c2 = acc[mt][nt][2], c3 = acc[mt][nt][3];
            if (RELU) {
                c0 = fmaxf(c0, 0.f); c1 = fmaxf(c1, 0.f);
                c2 = fmaxf(c2, 0.f); c3 = fmaxf(c3, 0.f);
            }
            if (ATOMIC) {
                if (row0 < M) {
                    atomicAdd(C + (size_t)row0 * ldc + col,     c0);
                    atomicAdd(C + (size_t)row0 * ldc + col + 1, c1);
                }
                if (row1 < M) {
                    atomicAdd(C + (size_t)row1 * ldc + col,     c2);
                    atomicAdd(C + (size_t)row1 * ldc + col + 1, c3);
                }
            } else {
                if (row0 < M)
                    *reinterpret_cast<float2*>(C + (size_t)row0 * ldc + col) = make_float2(c0, c1);
                if (row1 < M)
                    *reinterpret_cast<float2*>(C + (size_t)row1 * ldc + col) = make_float2(c2, c3);
            }
        }
    }
}

// ---------------- host ----------------
extern "C" void kernel_launch(void* const* d_in, const int* in_sizes, int n_in,
                              void* d_out, int out_size) {
    const float* A1    = (const float*)d_in[0];
    const int*   rows  = (const int*)  d_in[1];
    const int*   cols  = (const int*)  d_in[2];
    const float* vals  = (const float*)d_in[3];
    const int*   bidx  = (const int*)  d_in[4];
    const int*   blab  = (const int*)  d_in[5];
    const float* rawc  = (const float*)d_in[6];
    const float* nvec  = (const float*)d_in[7];
    const float* Lin1  = (const float*)d_in[8];
    const float* Lin1b = (const float*)d_in[9];
    const float* gc1w  = (const float*)d_in[10];
    const float* gc1b  = (const float*)d_in[11];
    const float* gc2w  = (const float*)d_in[12];
    const float* gc2b  = (const float*)d_in[13];
    const float* wgt   = (const float*)d_in[14];
    const float* lin1w = (const float*)d_in[15];
    const float* lin1b = (const float*)d_in[16];
    const float* cls   = (const float*)d_in[17];
    const float* clsb  = (const float*)d_in[18];
    float* out = (float*)d_out;

    int N = in_sizes[0] / 128;
    int E = in_sizes[1];
    int B = in_sizes[5];
    int L = in_sizes[4] / B;

    float *pScale, *pTA, *pT1, *pTM, *pT2, *pX2, *pG, *pH;
    cudaGetSymbolAddress((void**)&pScale, g_scale);
    cudaGetSymbolAddress((void**)&pTA, g_TA);
    cudaGetSymbolAddress((void**)&pT1, g_T1);
    cudaGetSymbolAddress((void**)&pTM, g_TM);
    cudaGetSymbolAddress((void**)&pT2, g_T2);
    cudaGetSymbolAddress((void**)&pX2, g_X2);
    cudaGetSymbolAddress((void**)&pG,  g_G);
    cudaGetSymbolAddress((void**)&pH,  g_H);

    cudaFuncSetAttribute(mmgemm_fused<2, true>,
                         cudaFuncAttributeMaxDynamicSharedMemorySize, FUSED_SMEM);
    cudaFuncSetAttribute(mmgemm_fused<1, false>,
                         cudaFuncAttributeMaxDynamicSharedMemorySize, FUSED_SMEM);

    int nwBlocks = (N + 7) / 8;
    int gG = (N + 127) / 128;
    int nb = (N + 255) / 256;

    // constants + bias tangents
    k_init<<<1, 32>>>(rawc, Lin1b, gc1b, gc2b);
    // CSR build
    k_zcnt<<<(N + 255) / 256, 256>>>(N);
    k_hist<<<(E + 255) / 256, 256>>>(rows, E);
    k_scan1<<<nb, 256>>>(N);
    k_scan2<<<1, 512>>>(nb);
    k_scan3<<<(N + 255) / 256, 256>>>(N, E);
    k_scatter<<<(E + 255) / 256, 256>>>(rows, cols, vals, E);
    // logmap0 scaling of A1
    k_scale<<<nwBlocks, 256>>>(A1, N);
    // layer-1 GEMMs + TBT fused: TA = TBT(T0@Lin1, ub0), T1 = TBT(T0@gc1w, ub1)
    mmgemm_fused<2, true><<<gG, 512, FUSED_SMEM>>>(
        N, A1, pScale, Lin1, gc1w, pTA, pT1, 0, 1);
    // SpMM #1 with fused mix -> TM
    k_csrmm<1><<<nwBlocks, 256>>>(pT1, pTM, nvec, N);
    // layer-2 GEMM + TBT fused: T2 = TBT(TM@gc2w, ub2)
    mmgemm_fused<1, false><<<gG, 512, FUSED_SMEM>>>(
        N, pTM, nullptr, gc2w, nullptr, pT2, nullptr, 2, 0);
    // SpMM #2 with fused EL -> X2
    k_csrmm<2><<<nwBlocks, 256>>>(pT2, pX2, nullptr, N);
    // batch gather + appended sum row
    k_gather<<<B, 128>>>(bidx, L);
    // H = relu(G @ weight)
    int M3 = B * (L + 1);
    mmgemm<128,64,32,4,2,false,true,false,false><<<dim3((M3 + 127) / 128, 1, 1), 256>>>(
        M3, 64, 128, 128, pG, 128, wgt, 64, pH, 64, nullptr);
    // OUT = H @ lin1_w^T, split-K atomic into d_out+1
    k_zero<<<1024, 256>>>(out, out_size);
    int KD = (L + 1) * 64;
    int kChunk = 832;
    int zs = (KD + kChunk - 1) / kChunk;
    mmgemm<128,128,32,4,4,true,false,false,true><<<dim3((B + 127) / 128, 1, zs), 512>>>(
        B, 128, KD, kChunk, pH, KD, lin1w, KD, out + 1, 128, nullptr);
    k_addbias<<<(B * 128 + 255) / 256, 256>>>(out + 1, lin1b, B * 128);
    // loss + finalize
    k_loss<<<(B + 7) / 8, 256>>>(out + 1, cls, clsb, blab, B);
    k_final<<<1, 1>>>(out, out_size, B);
}

// round 10
// speedup vs baseline: 1.1365x; 1.1365x over previous
#include <cuda_runtime.h>
#include <cuda_bf16.h>
#include <cstdint>
#include <math.h>

// ---------------- problem-size constants (from reference) ----------------
#define NMAXN 100000
#define EMAXE 1600000
#define BMAXB 4096
#define LP1   51

#define EPSF 1e-7f
#define MINN 1e-15f
#define MAXN 1e6f

// ---------------- device scratch (static: no allocations allowed) --------
__device__ float g_scale[NMAXN];
__device__ float g_U1[NMAXN * 128];
__device__ float g_U2[NMAXN * 128];
__device__ float g_TA[NMAXN * 128];
__device__ float g_T1[NMAXN * 128];
__device__ float g_TM[NMAXN * 128];
__device__ float g_T2[NMAXN * 128];
__device__ float g_X2[NMAXN * 128];
__device__ float g_P [BMAXB * (LP1 - 1) * 64];
__device__ float g_H [BMAXB * LP1 * 64];
__device__ float g_ub[3][128];
__device__ float g_cp[3];        // c, K=1/c, sqrtK
__device__ float g_loss;
// CSR scratch
__device__ int   g_cnt[NMAXN];
__device__ int   g_off[NMAXN + 1];
__device__ int   g_cur[NMAXN];
__device__ int   g_ccol[EMAXE];
__device__ float g_cval[EMAXE];
__device__ int   g_bsum[512];

// ---------------- small device helpers ----------------
__device__ __forceinline__ float wsum(float v) {
#pragma unroll
    for (int o = 16; o; o >>= 1) v += __shfl_xor_sync(0xffffffffu, v, o);
    return v;
}

__device__ __forceinline__ float f_arcosh(float x) {
    x = fmaxf(x, 1.0f + EPSF);
    return logf(x + sqrtf(x * x - 1.0f));
}

// exp0log0: logmap0(proj(expmap0(u))) with the reference's clamps.
__device__ __forceinline__ void d_EL(float* u, float sqrtK, float Kc) {
    float sq = wsum(u[0]*u[0] + u[1]*u[1] + u[2]*u[2] + u[3]*u[3]);
    float xn = fmaxf(sqrtf(sq), MINN);
    float th = xn / sqrtK;
    float coef = sqrtK * sinhf(th) / xn;
    u[0] *= coef; u[1] *= coef; u[2] *= coef; u[3] *= coef;
    float rs = wsum(u[0]*u[0] + u[1]*u[1] + u[2]*u[2] + u[3]*u[3]);
    float x0 = sqrtf(Kc + rs);
    float yn = fmaxf(sqrtf(rs), MINN);
    float s = sqrtK * f_arcosh(x0 / sqrtK);
    float f = s / yn;
    u[0] *= f; u[1] *= f; u[2] *= f; u[3] *= f;
}

// tangent u -> expmap0 -> mobius_add(point, bias) -> logmap0 -> tangent (in place)
__device__ __forceinline__ void d_TBT(float* u, const float* ub, float sqrtK,
                                      float Kc, int lane) {
    float sq = wsum(u[0]*u[0] + u[1]*u[1] + u[2]*u[2] + u[3]*u[3]);
    float xn = fmaxf(sqrtf(sq), MINN);
    float th = xn / sqrtK;
    float coef = sqrtK * sinhf(th) / xn;
    float a0 = coef*u[0], a1 = coef*u[1], a2 = coef*u[2], a3 = coef*u[3];
    float sp2 = wsum(a0*a0 + a1*a1 + a2*a2 + a3*a3);
    float x0 = sqrtf(Kc + sp2);
    float yn = fmaxf(sqrtf(sp2), MINN);
    float y0 = a0/yn, y1 = a1/yn, y2 = a2/yn, y3 = a3/yn;
    float ub0 = ub[lane*4+0], ub1 = ub[lane*4+1], ub2 = ub[lane*4+2], ub3 = ub[lane*4+3];
    float alpha = wsum(y0*ub0 + y1*ub1 + y2*ub2 + y3*ub3) / sqrtK;
    float c2 = alpha * (sqrtK - x0);
    float w0 = ub0 - c2*y0, w1 = ub1 - c2*y1, w2 = ub2 - c2*y2, w3 = ub3 - c2*y3;
    float wt = wsum(a0*w0 + a1*w1 + a2*w2 + a3*w3) / fmaxf(x0, EPSF);
    float md = wsum(w0*w0 + w1*w1 + w2*w2 + w3*w3) - wt*wt;
    float normu = sqrtf(fmaxf(md, EPSF));
    normu = fminf(normu, MAXN);
    float th2 = fmaxf(normu / sqrtK, MINN);
    float ch = coshf(th2);
    float sh = sinhf(th2) / th2;
    float r0 = ch*a0 + sh*w0, r1 = ch*a1 + sh*w1, r2 = ch*a2 + sh*w2, r3 = ch*a3 + sh*w3;
    float rs2 = wsum(r0*r0 + r1*r1 + r2*r2 + r3*r3);
    float x0n = sqrtf(Kc + rs2);
    float yn2 = fmaxf(sqrtf(rs2), MINN);
    float s = sqrtK * f_arcosh(x0n / sqrtK);
    float f = s / yn2;
    u[0] = f*r0; u[1] = f*r1; u[2] = f*r2; u[3] = f*r3;
}

// ---------------- elementwise / graph kernels ----------------

__global__ void k_init(const float* __restrict__ rawc,
                       const float* __restrict__ b0,
                       const float* __restrict__ b1,
                       const float* __restrict__ b2) {
    int lane = threadIdx.x;
    float rc = rawc[0];
    float c = fmaxf(rc, 0.f) + log1pf(expf(-fabsf(rc))) + 1e-5f;
    float Kc = 1.f / c;
    float sqrtK = sqrtf(Kc);
    if (lane == 0) { g_cp[0] = c; g_cp[1] = Kc; g_cp[2] = sqrtK; g_loss = 0.f; }
    const float* bs[3] = {b0, b1, b2};
#pragma unroll
    for (int k = 0; k < 3; k++) {
        float u[4];
#pragma unroll
        for (int i = 0; i < 4; i++) u[i] = bs[k][lane*4 + i];
        if (lane == 0) u[0] = 0.f;
        d_EL(u, sqrtK, Kc);
#pragma unroll
        for (int i = 0; i < 4; i++) g_ub[k][lane*4 + i] = u[i];
    }
}

__global__ void k_scale(const float* __restrict__ A1, int N) {
    int w = (blockIdx.x * blockDim.x + threadIdx.x) >> 5;
    if (w >= N) return;
    int lane = threadIdx.x & 31;
    float sqrtK = g_cp[2];
    const float4 v = *((const float4*)(A1 + (size_t)w * 128) + lane);
    float s4 = v.x*v.x + v.y*v.y + v.z*v.z + v.w*v.w;
    if (lane == 0) s4 -= v.x*v.x;
    float sq = wsum(s4);
    if (lane == 0) {
        float yn = fmaxf(sqrtf(sq), MINN);
        float s = sqrtK * f_arcosh(__ldg(A1 + (size_t)w * 128) / sqrtK);
        g_scale[w] = s / yn;
    }
}

__global__ void k_l1nl(int N) {
    int w = (blockIdx.x * blockDim.x + threadIdx.x) >> 5;
    if (w >= N) return;
    int lane = threadIdx.x & 31;
    float sqrtK = g_cp[2], Kc = g_cp[1];
    float u[4];
    float4 v = *((const float4*)(g_U1 + (size_t)w * 128) + lane);
    u[0]=v.x; u[1]=v.y; u[2]=v.z; u[3]=v.w; if (lane==0) u[0]=0.f;
    d_TBT(u, g_ub[0], sqrtK, Kc, lane);
    *((float4*)(g_TA + (size_t)w * 128) + lane) = make_float4(u[0],u[1],u[2],u[3]);
    v = *((const float4*)(g_U2 + (size_t)w * 128) + lane);
    u[0]=v.x; u[1]=v.y; u[2]=v.z; u[3]=v.w; if (lane==0) u[0]=0.f;
    d_TBT(u, g_ub[1], sqrtK, Kc, lane);
    *((float4*)(g_T1 + (size_t)w * 128) + lane) = make_float4(u[0],u[1],u[2],u[3]);
}

__global__ void k_l2nl(int N) {
    int w = (blockIdx.x * blockDim.x + threadIdx.x) >> 5;
    if (w >= N) return;
    int lane = threadIdx.x & 31;
    float sqrtK = g_cp[2], Kc = g_cp[1];
    float u[4];
    float4 v = *((const float4*)(g_U1 + (size_t)w * 128) + lane);
    u[0]=v.x; u[1]=v.y; u[2]=v.z; u[3]=v.w; if (lane==0) u[0]=0.f;
    d_TBT(u, g_ub[2], sqrtK, Kc, lane);
    *((float4*)(g_T2 + (size_t)w * 128) + lane) = make_float4(u[0],u[1],u[2],u[3]);
}

__global__ void k_zero(float* __restrict__ p, int n) {
    int i = blockIdx.x * blockDim.x + threadIdx.x;
    int st = gridDim.x * blockDim.x;
    for (; i < n; i += st) p[i] = 0.f;
}

// ---------------- CSR build ----------------
__global__ void k_zcnt(int N) {
    int i = blockIdx.x * blockDim.x + threadIdx.x;
    if (i < N) g_cnt[i] = 0;
}
__global__ void k_hist(const int* __restrict__ rows, int E) {
    int e = blockIdx.x * blockDim.x + threadIdx.x;
    if (e < E) atomicAdd(&g_cnt[__ldg(rows + e)], 1);
}
__global__ void k_scan1(int N) {
    __shared__ int sh[256];
    int b = blockIdx.x, t = threadIdx.x;
    int idx = b * 256 + t;
    int v = (idx < N) ? g_cnt[idx] : 0;
    sh[t] = v;
    __syncthreads();
    for (int o = 1; o < 256; o <<= 1) {
        int x = (t >= o) ? sh[t - o] : 0;
        __syncthreads();
        sh[t] += x;
        __syncthreads();
    }
    if (idx < N) g_off[idx] = sh[t] - v;
    if (t == 255) g_bsum[b] = sh[255];
}
__global__ void k_scan2(int nb) {
    __shared__ int sh[512];
    int t = threadIdx.x;
    int v = (t < nb) ? g_bsum[t] : 0;
    sh[t] = v;
    __syncthreads();
    for (int o = 1; o < 512; o <<= 1) {
        int x = (t >= o) ? sh[t - o] : 0;
        __syncthreads();
        sh[t] += x;
        __syncthreads();
    }
    if (t < nb) g_bsum[t] = sh[t] - v;
}
__global__ void k_scan3(int N, int E) {
    int i = blockIdx.x * blockDim.x + threadIdx.x;
    if (i < N) {
        int o = g_off[i] + g_bsum[i >> 8];
        g_off[i] = o;
        g_cur[i] = o;
    }
    if (i == 0) g_off[N] = E;
}
__global__ void k_scatter(const int* __restrict__ rows, const int* __restrict__ cols,
                          const float* __restrict__ vals, int E) {
    int e = blockIdx.x * blockDim.x + threadIdx.x;
    if (e >= E) return;
    int r = __ldg(rows + e);
    int pos = atomicAdd(&g_cur[r], 1);
    g_ccol[pos] = __ldg(cols + e);
    g_cval[pos] = __ldg(vals + e);
}

// ---------------- CSR SpMM with fused nonlinearity ---------------------------
template<int FUSE>
__global__ void k_csrmm(const float* __restrict__ T, float* __restrict__ OUT,
                        const float* __restrict__ nvec, int N) {
    int w = (blockIdx.x * blockDim.x + threadIdx.x) >> 5;
    if (w >= N) return;
    int lane = threadIdx.x & 31;
    int e0 = __ldg(g_off + w);
    int e1 = __ldg(g_off + w + 1);
    float a[4] = {0.f, 0.f, 0.f, 0.f};
    int e = e0;
    for (; e + 2 <= e1; e += 2) {
        int c0 = __ldg(g_ccol + e);
        int c1 = __ldg(g_ccol + e + 1);
        float v0 = __ldg(g_cval + e);
        float v1 = __ldg(g_cval + e + 1);
        float4 t0 = __ldg((const float4*)(T + (size_t)c0 * 128) + lane);
        float4 t1 = __ldg((const float4*)(T + (size_t)c1 * 128) + lane);
        a[0] += t0.x * v0 + t1.x * v1;
        a[1] += t0.y * v0 + t1.y * v1;
        a[2] += t0.z * v0 + t1.z * v1;
        a[3] += t0.w * v0 + t1.w * v1;
    }
    if (e < e1) {
        int c0 = __ldg(g_ccol + e);
        float v0 = __ldg(g_cval + e);
        float4 t0 = __ldg((const float4*)(T + (size_t)c0 * 128) + lane);
        a[0] += t0.x * v0; a[1] += t0.y * v0; a[2] += t0.z * v0; a[3] += t0.w * v0;
    }
    float sqrtK = g_cp[2], Kc = g_cp[1];
    if (FUSE == 1) {
        d_EL(a, sqrtK, Kc);
        float nv = __ldg(nvec + w);
        float om = 1.f - nv;
#pragma unroll
        for (int i = 0; i < 4; i++) a[i] *= om;
        d_EL(a, sqrtK, Kc);
        float b[4];
        float4 v = *((const float4*)(g_TA + (size_t)w * 128) + lane);
        b[0]=v.x*nv; b[1]=v.y*nv; b[2]=v.z*nv; b[3]=v.w*nv;
        d_EL(b, sqrtK, Kc);
#pragma unroll
        for (int i = 0; i < 4; i++) a[i] += b[i];
        d_EL(a, sqrtK, Kc);
    } else if (FUSE == 2) {
        d_EL(a, sqrtK, Kc);
    }
    *((float4*)(OUT + (size_t)w * 128) + lane) = make_float4(a[0], a[1], a[2], a[3]);
}

// H rows b*51+l = relu(P[b*50+l]) for l<50; H row b*51+50 = relu(sum_l P[b*50+l])
__global__ void k_hsum(int B, int L) {
    int b = blockIdx.x;
    int j = threadIdx.x;            // 64 threads
    const float* Pb = g_P + (size_t)b * L * 64;
    float* Hb = g_H + (size_t)b * (L + 1) * 64;
    float s = 0.f;
    for (int l = 0; l < L; l++) {
        float p = Pb[(size_t)l * 64 + j];
        s += p;
        Hb[(size_t)l * 64 + j] = fmaxf(p, 0.f);
    }
    Hb[(size_t)L * 64 + j] = fmaxf(s, 0.f);
}

__global__ void k_addbias(float* __restrict__ o, const float* __restrict__ bias, int n) {
    int i = blockIdx.x * blockDim.x + threadIdx.x;
    if (i < n) o[i] += __ldg(bias + (i & 127));
}

__global__ void k_loss(const float* __restrict__ sel, const float* __restrict__ cls,
                       const float* __restrict__ cb, const int* __restrict__ lab, int B) {
    int b = (blockIdx.x * blockDim.x + threadIdx.x) >> 5;
    if (b >= B) return;
    int lane = threadIdx.x & 31;
    const float* row = sel + (size_t)b * 128;
    float d0 = 0.f, d1 = 0.f;
#pragma unroll
    for (int i = 0; i < 4; i++) {
        int d = lane * 4 + i;
        float o = row[d];
        d0 += o * __ldg(cls + d * 2 + 0);
        d1 += o * __ldg(cls + d * 2 + 1);
    }
    d0 = wsum(d0); d1 = wsum(d1);
    if (lane == 0) {
        float p0 = d0 + __ldg(cb + 0);
        float p1 = d1 + __ldg(cb + 1);
        float m = fmaxf(p0, p1);
        float lse = m + logf(expf(p0 - m) + expf(p1 - m));
        int y = __ldg(lab + b);
        float lp = (y == 0 ? p0 : p1) - lse;
        atomicAdd(&g_loss, lp);
    }
}

__global__ void k_final(float* __restrict__ out, int out_size, int B) {
    out[0] = -g_loss / (float)B;
    out[out_size - 1] = g_cp[0];
}

// ---------------- mma.sync helpers ----------------
__device__ __forceinline__ void ldm_x4(uint32_t* r, uint32_t addr) {
    asm volatile("ldmatrix.sync.aligned.m8n8.x4.shared.b16 {%0,%1,%2,%3}, [%4];"
        : "=r"(r[0]), "=r"(r[1]), "=r"(r[2]), "=r"(r[3]) : "r"(addr));
}
__device__ __forceinline__ void mma_bf16(float* c, const uint32_t* a, const uint32_t* b) {
    asm volatile("mma.sync.aligned.m16n8k16.row.col.f32.bf16.bf16.f32 "
        "{%0,%1,%2,%3}, {%4,%5,%6,%7}, {%8,%9}, {%0,%1,%2,%3};"
        : "+f"(c[0]), "+f"(c[1]), "+f"(c[2]), "+f"(c[3])
        : "r"(a[0]), "r"(a[1]), "r"(a[2]), "r"(a[3]), "r"(b[0]), "r"(b[1]));
}
__device__ __forceinline__ uint32_t pack_hi2(float x, float y) {
    __nv_bfloat16 hx = __float2bfloat16(x), hy = __float2bfloat16(y);
    return ((uint32_t)__bfloat16_as_ushort(hy) << 16) | __bfloat16_as_ushort(hx);
}
__device__ __forceinline__ uint32_t pack_lo2(float x, float y) {
    __nv_bfloat16 hx = __float2bfloat16(x), hy = __float2bfloat16(y);
    __nv_bfloat16 lx = __float2bfloat16(x - __bfloat162float(hx));
    __nv_bfloat16 ly = __float2bfloat16(y - __bfloat162float(hy));
    return ((uint32_t)__bfloat16_as_ushort(ly) << 16) | __bfloat16_as_ushort(lx);
}

// ---------------- dual-output GEMM: A resident in smem (K=128, N=128) --------
#define DLDK 136
#define DUAL_SMEM (4 * 128 * DLDK * 2)
__global__ void __launch_bounds__(512)
mmgemm_dual(int M, const float* __restrict__ A, const float* __restrict__ scale,
            const float* __restrict__ B0, const float* __restrict__ B1,
            float* __restrict__ C0, float* __restrict__ C1) {
    extern __shared__ __align__(16) __nv_bfloat16 dsm[];
    __nv_bfloat16* AsH = dsm;
    __nv_bfloat16* AsL = AsH + 128 * DLDK;
    __nv_bfloat16* BsH = AsL + 128 * DLDK;
    __nv_bfloat16* BsL = BsH + 128 * DLDK;

    int tid = threadIdx.x;
    int lane = tid & 31;
    int wid = tid >> 5;
    int wm = wid >> 2;
    int wn = wid & 3;
    int m0 = blockIdx.x * 128;

#pragma unroll
    for (int t = 0; t < 8; t++) {
        int i = tid + t * 512;
        int r = i >> 5;
        int kc = (i & 31) * 4;
        int gr = m0 + r;
        float4 v = make_float4(0.f, 0.f, 0.f, 0.f);
        if (gr < M) {
            v = *reinterpret_cast<const float4*>(A + (size_t)gr * 128 + kc);
            float s = __ldg(scale + gr);
            v.x *= s; v.y *= s; v.z *= s; v.w *= s;
            if (kc == 0) v.x = 0.f;
        }
        *(uint32_t*)&AsH[r * DLDK + kc]     = pack_hi2(v.x, v.y);
        *(uint32_t*)&AsH[r * DLDK + kc + 2] = pack_hi2(v.z, v.w);
        *(uint32_t*)&AsL[r * DLDK + kc]     = pack_lo2(v.x, v.y);
        *(uint32_t*)&AsL[r * DLDK + kc + 2] = pack_lo2(v.z, v.w);
    }

    int a_row = (lane & 7) + ((lane >> 3) & 1) * 8;
    int a_kof = (lane >> 4) * 8;
    int b_row = (lane & 7) + (lane >> 4) * 8;
    int b_kof = ((lane >> 3) & 1) * 8;

    float acc[2][4][4];

    for (int pass = 0; pass < 2; pass++) {
        const float* Bg = pass ? B1 : B0;
        float* Cg = pass ? C1 : C0;
#pragma unroll
        for (int t = 0; t < 8; t++) {
            int i = tid + t * 512;
            int kk = i >> 5;
            int nc = (i & 31) * 4;
            float4 v = *reinterpret_cast<const float4*>(Bg + (size_t)kk * 128 + nc);
            float vv[4] = {v.x, v.y, v.z, v.w};
#pragma unroll
            for (int j = 0; j < 4; j++) {
                __nv_bfloat16 h = __float2bfloat16(vv[j]);
                BsH[(nc + j) * DLDK + kk] = h;
                BsL[(nc + j) * DLDK + kk] = __float2bfloat16(vv[j] - __bfloat162float(h));
            }
        }
        __syncthreads();

#pragma unroll
        for (int i = 0; i < 2; i++)
#pragma unroll
            for (int j = 0; j < 4; j++)
#pragma unroll
                for (int q = 0; q < 4; q++) acc[i][j][q] = 0.f;

#pragma unroll
        for (int kk = 0; kk < 128; kk += 16) {
            uint32_t ah[2][4], al[2][4], bh[2][4], bl[2][4];
#pragma unroll
            for (int mt = 0; mt < 2; mt++) {
                int row = wm * 32 + mt * 16 + a_row;
                int col = kk + a_kof;
                ldm_x4(ah[mt], (uint32_t)__cvta_generic_to_shared(&AsH[row * DLDK + col]));
                ldm_x4(al[mt], (uint32_t)__cvta_generic_to_shared(&AsL[row * DLDK + col]));
            }
#pragma unroll
            for (int np = 0; np < 2; np++) {
                int nrow = wn * 32 + np * 16 + b_row;
                int col = kk + b_kof;
                ldm_x4(bh[np], (uint32_t)__cvta_generic_to_shared(&BsH[nrow * DLDK + col]));
                ldm_x4(bl[np], (uint32_t)__cvta_generic_to_shared(&BsL[nrow * DLDK + col]));
            }
#pragma unroll
            for (int np = 0; np < 2; np++)
#pragma unroll
                for (int mt = 0; mt < 2; mt++) {
                    mma_bf16(acc[mt][2*np],   ah[mt], bh[np]);
                    mma_bf16(acc[mt][2*np+1], ah[mt], bh[np] + 2);
                }
#pragma unroll
            for (int np = 0; np < 2; np++)
#pragma unroll
                for (int mt = 0; mt < 2; mt++) {
                    mma_bf16(acc[mt][2*np],   ah[mt], bl[np]);
                    mma_bf16(acc[mt][2*np+1], ah[mt], bl[np] + 2);
                }
#pragma unroll
            for (int np = 0; np < 2; np++)
#pragma unroll
                for (int mt = 0; mt < 2; mt++) {
                    mma_bf16(acc[mt][2*np],   al[mt], bh[np]);
                    mma_bf16(acc[mt][2*np+1], al[mt], bh[np] + 2);
                }
        }

#pragma unroll
        for (int mt = 0; mt < 2; mt++) {
            int row0 = m0 + wm * 32 + mt * 16 + (lane >> 2);
            int row1 = row0 + 8;
#pragma unroll
            for (int nt = 0; nt < 4; nt++) {
                int col = wn * 32 + nt * 8 + (lane & 3) * 2;
                if (row0 < M)
                    *reinterpret_cast<float2*>(Cg + (size_t)row0 * 128 + col) =
                        make_float2(acc[mt][nt][0], acc[mt][nt][1]);
                if (row1 < M)
                    *reinterpret_cast<float2*>(Cg + (size_t)row1 * 128 + col) =
                        make_float2(acc[mt][nt][2], acc[mt][nt][3]);
            }
        }
        __syncthreads();
    }
}

// ---------------- general mma.sync GEMM (pipelined, term-reordered) ----------
// GATHER: A row r is X2-style gathered via gidx[r] (lda applies to gathered base).
template<int BM, int BN, int BK, int NWM, int NWN, bool BT, bool RELU, bool ASCALE,
         bool ATOMIC, bool GATHER>
__global__ void __launch_bounds__(NWM * NWN * 32)
mmgemm(int M, int N, int K, int kChunk,
       const float* __restrict__ A, int lda,
       const float* __restrict__ B, int ldb,
       float* __restrict__ C, int ldc,
       const float* __restrict__ scale, const int* __restrict__ gidx) {
    constexpr int THREADS = NWM * NWN * 32;
    constexpr int WM = BM / NWM;
    constexpr int WN = BN / NWN;
    constexpr int MT = WM / 16;
    constexpr int NT = WN / 8;
    constexpr int NP = NT / 2;
    constexpr int LDK = BK + 8;
    constexpr int NA = (BM * (BK / 4) + THREADS - 1) / THREADS;
    constexpr int NBCNT = BT ? BN * (BK / 4) : BK * (BN / 4);
    constexpr int NB = (NBCNT + THREADS - 1) / THREADS;

    __shared__ __align__(16) __nv_bfloat16 AsH[BM * LDK];
    __shared__ __align__(16) __nv_bfloat16 AsL[BM * LDK];
    __shared__ __align__(16) __nv_bfloat16 BsH[BN * LDK];
    __shared__ __align__(16) __nv_bfloat16 BsL[BN * LDK];

    int tid = threadIdx.x;
    int lane = tid & 31;
    int wid = tid >> 5;
    int wm = wid / NWN;
    int wn = wid % NWN;
    int m0 = blockIdx.x * BM;
    int n0 = blockIdx.y * BN;
    int kStart = blockIdx.z * kChunk;
    int kEnd = min(K, kStart + kChunk);

    float acc[MT][NT][4];
#pragma unroll
    for (int i = 0; i < MT; i++)
#pragma unroll
        for (int j = 0; j < NT; j++)
#pragma unroll
            for (int q = 0; q < 4; q++) acc[i][j][q] = 0.f;

    float4 pa[NA]; float ps[NA]; float4 pb[NB];

    auto loadA = [&](int k0) {
#pragma unroll
        for (int t = 0; t < NA; t++) {
            int i = tid + t * THREADS;
            float4 v = make_float4(0.f, 0.f, 0.f, 0.f);
            float s = 0.f;
            if (i < BM * (BK / 4)) {
                int r = i / (BK / 4);
                int kc = (i % (BK / 4)) * 4;
                int gr = m0 + r;
                if (gr < M) {
                    size_t ar = GATHER ? (size_t)__ldg(gidx + gr) : (size_t)gr;
                    v = *reinterpret_cast<const float4*>(A + ar * lda + k0 + kc);
                    if (ASCALE) s = __ldg(scale + gr);
                }
            }
            pa[t] = v;
            if (ASCALE) ps[t] = s;
        }
    };
    auto storeA = [&](int k0) {
#pragma unroll
        for (int t = 0; t < NA; t++) {
            int i = tid + t * THREADS;
            if (i < BM * (BK / 4)) {
                int r = i / (BK / 4);
                int kc = (i % (BK / 4)) * 4;
                float4 v = pa[t];
                if (ASCALE) {
                    float s = ps[t];
                    v.x *= s; v.y *= s; v.z *= s; v.w *= s;
                    if (k0 + kc == 0) v.x = 0.f;
                }
                *(uint32_t*)&AsH[r * LDK + kc]     = pack_hi2(v.x, v.y);
                *(uint32_t*)&AsH[r * LDK + kc + 2] = pack_hi2(v.z, v.w);
                *(uint32_t*)&AsL[r * LDK + kc]     = pack_lo2(v.x, v.y);
                *(uint32_t*)&AsL[r * LDK + kc + 2] = pack_lo2(v.z, v.w);
            }
        }
    };
    auto loadB = [&](int k0) {
#pragma unroll
        for (int t = 0; t < NB; t++) {
            int i = tid + t * THREADS;
            float4 v = make_float4(0.f, 0.f, 0.f, 0.f);
            if (i < NBCNT) {
                if (BT) {
                    int r = i / (BK / 4);
                    int kc = (i % (BK / 4)) * 4;
                    v = *reinterpret_cast<const float4*>(B + (size_t)(n0 + r) * ldb + k0 + kc);
                } else {
                    int kk = i / (BN / 4);
                    int nc = (i % (BN / 4)) * 4;
                    v = *reinterpret_cast<const float4*>(B + (size_t)(k0 + kk) * ldb + n0 + nc);
                }
            }
            pb[t] = v;
        }
    };
    auto storeB = [&]() {
#pragma unroll
        for (int t = 0; t < NB; t++) {
            int i = tid + t * THREADS;
            if (i < NBCNT) {
                float4 v = pb[t];
                if (BT) {
                    int r = i / (BK / 4);
                    int kc = (i % (BK / 4)) * 4;
                    *(uint32_t*)&BsH[r * LDK + kc]     = pack_hi2(v.x, v.y);
                    *(uint32_t*)&BsH[r * LDK + kc + 2] = pack_hi2(v.z, v.w);
                    *(uint32_t*)&BsL[r * LDK + kc]     = pack_lo2(v.x, v.y);
                    *(uint32_t*)&BsL[r * LDK + kc + 2] = pack_lo2(v.z, v.w);
                } else {
                    int kk = i / (BN / 4);
                    int nc = (i % (BN / 4)) * 4;
                    float vv[4] = {v.x, v.y, v.z, v.w};
#pragma unroll
                    for (int j = 0; j < 4; j++) {
                        __nv_bfloat16 h = __float2bfloat16(vv[j]);
                        BsH[(nc + j) * LDK + kk] = h;
                        BsL[(nc + j) * LDK + kk] = __float2bfloat16(vv[j] - __bfloat162float(h));
                    }
                }
            }
        }
    };

    int a_row = (lane & 7) + ((lane >> 3) & 1) * 8;
    int a_kof = (lane >> 4) * 8;
    int b_row = (lane & 7) + (lane >> 4) * 8;
    int b_kof = ((lane >> 3) & 1) * 8;

    loadA(kStart);
    loadB(kStart);

    for (int k0 = kStart; k0 < kEnd; k0 += BK) {
        storeA(k0);
        storeB();
        __syncthreads();
        if (k0 + BK < kEnd) {
            loadA(k0 + BK);
            loadB(k0 + BK);
        }
#pragma unroll
        for (int kk = 0; kk < BK; kk += 16) {
            uint32_t ah[MT][4], al[MT][4], bh[NP][4], bl[NP][4];
#pragma unroll
            for (int mt = 0; mt < MT; mt++) {
                int row = wm * WM + mt * 16 + a_row;
                int col = kk + a_kof;
                ldm_x4(ah[mt], (uint32_t)__cvta_generic_to_shared(&AsH[row * LDK + col]));
                ldm_x4(al[mt], (uint32_t)__cvta_generic_to_shared(&AsL[row * LDK + col]));
            }
#pragma unroll
            for (int np = 0; np < NP; np++) {
                int nrow = wn * WN + np * 16 + b_row;
                int col = kk + b_kof;
                ldm_x4(bh[np], (uint32_t)__cvta_generic_to_shared(&BsH[nrow * LDK + col]));
                ldm_x4(bl[np], (uint32_t)__cvta_generic_to_shared(&BsL[nrow * LDK + col]));
            }
#pragma unroll
            for (int np = 0; np < NP; np++)
#pragma unroll
                for (int mt = 0; mt < MT; mt++) {
                    mma_bf16(acc[mt][2*np],   ah[mt], bh[np]);
                    mma_bf16(acc[mt][2*np+1], ah[mt], bh[np] + 2);
                }
#pragma unroll
            for (int np = 0; np < NP; np++)
#pragma unroll
                for (int mt = 0; mt < MT; mt++) {
                    mma_bf16(acc[mt][2*np],   ah[mt], bl[np]);
                    mma_bf16(acc[mt][2*np+1], ah[mt], bl[np] + 2);
                }
#pragma unroll
            for (int np = 0; np < NP; np++)
#pragma unroll
                for (int mt = 0; mt < MT; mt++) {
                    mma_bf16(acc[mt][2*np],   al[mt], bh[np]);
                    mma_bf16(acc[mt][2*np+1], al[mt], bh[np] + 2);
                }
        }
        __syncthreads();
    }

#pragma unroll
    for (int mt = 0; mt < MT; mt++) {
        int row0 = m0 + wm * WM + mt * 16 + (lane >> 2);
        int row1 = row0 + 8;
#pragma unroll
        for (int nt = 0; nt < NT; nt++) {
            int col = n0 + wn * WN + nt * 8 + (lane & 3) * 2;
            float c0 = acc[mt][nt][0], c1 = acc[mt][nt][1];
            float c2 = acc[mt][nt][2], c3 = acc[mt][nt][3];
            if (RELU) {
                c0 = fmaxf(c0, 0.f); c1 = fmaxf(c1, 0.f);
                c2 = fmaxf(c2, 0.f); c3 = fmaxf(c3, 0.f);
            }
            if (ATOMIC) {
                if (row0 < M) {
                    atomicAdd(C + (size_t)row0 * ldc + col,     c0);
                    atomicAdd(C + (size_t)row0 * ldc + col + 1, c1);
                }
                if (row1 < M) {
                    atomicAdd(C + (size_t)row1 * ldc + col,     c2);
                    atomicAdd(C + (size_t)row1 * ldc + col + 1, c3);
                }
            } else {
                if (row0 < M)
                    *reinterpret_cast<float2*>(C + (size_t)row0 * ldc + col) = make_float2(c0, c1);
                if (row1 < M)
                    *reinterpret_cast<float2*>(C + (size_t)row1 * ldc + col) = make_float2(c2, c3);
            }
        }
    }
}

// ---------------- host ----------------
extern "C" void kernel_launch(void* const* d_in, const int* in_sizes, int n_in,
                              void* d_out, int out_size) {
    const float* A1    = (const float*)d_in[0];
    const int*   rows  = (const int*)  d_in[1];
    const int*   cols  = (const int*)  d_in[2];
    const float* vals  = (const float*)d_in[3];
    const int*   bidx  = (const int*)  d_in[4];
    const int*   blab  = (const int*)  d_in[5];
    const float* rawc  = (const float*)d_in[6];
    const float* nvec  = (const float*)d_in[7];
    const float* Lin1  = (const float*)d_in[8];
    const float* Lin1b = (const float*)d_in[9];
    const float* gc1w  = (const float*)d_in[10];
    const float* gc1b  = (const float*)d_in[11];
    const float* gc2w  = (const float*)d_in[12];
    const float* gc2b  = (const float*)d_in[13];
    const float* wgt   = (const float*)d_in[14];
    const float* lin1w = (const float*)d_in[15];
    const float* lin1b = (const float*)d_in[16];
    const float* cls   = (const float*)d_in[17];
    const float* clsb  = (const float*)d_in[18];
    float* out = (float*)d_out;

    int N = in_sizes[0] / 128;
    int E = in_sizes[1];
    int B = in_sizes[5];
    int L = in_sizes[4] / B;

    float *pScale, *pU1, *pU2, *pTA, *pT1, *pTM, *pT2, *pX2, *pP, *pH;
    cudaGetSymbolAddress((void**)&pScale, g_scale);
    cudaGetSymbolAddress((void**)&pU1, g_U1);
    cudaGetSymbolAddress((void**)&pU2, g_U2);
    cudaGetSymbolAddress((void**)&pTA, g_TA);
    cudaGetSymbolAddress((void**)&pT1, g_T1);
    cudaGetSymbolAddress((void**)&pTM, g_TM);
    cudaGetSymbolAddress((void**)&pT2, g_T2);
    cudaGetSymbolAddress((void**)&pX2, g_X2);
    cudaGetSymbolAddress((void**)&pP,  g_P);
    cudaGetSymbolAddress((void**)&pH,  g_H);

    cudaFuncSetAttribute(mmgemm_dual,
                         cudaFuncAttributeMaxDynamicSharedMemorySize, DUAL_SMEM);

    int nwBlocks = (N + 7) / 8;
    int gG = (N + 127) / 128;
    int nb = (N + 255) / 256;

    // constants + bias tangents
    k_init<<<1, 32>>>(rawc, Lin1b, gc1b, gc2b);
    // CSR build
    k_zcnt<<<(N + 255) / 256, 256>>>(N);
    k_hist<<<(E + 255) / 256, 256>>>(rows, E);
    k_scan1<<<nb, 256>>>(N);
    k_scan2<<<1, 512>>>(nb);
    k_scan3<<<(N + 255) / 256, 256>>>(N, E);
    k_scatter<<<(E + 255) / 256, 256>>>(rows, cols, vals, E);
    // logmap0 scaling of A1
    k_scale<<<nwBlocks, 256>>>(A1, N);
    // U1 = T0 @ Lin1 ; U2 = T0 @ gc1_w — dual GEMM, A converted once
    mmgemm_dual<<<gG, 512, DUAL_SMEM>>>(N, A1, pScale, Lin1, gc1w, pU1, pU2);
    // nonlinear: t_a1 (Lin1 path) and T1 (gc1 path)
    k_l1nl<<<nwBlocks, 256>>>(N);
    // SpMM #1 with fused mix -> TM
    k_csrmm<1><<<nwBlocks, 256>>>(pT1, pTM, nvec, N);
    // U3 = Tm @ gc2_w (into g_U1)
    mmgemm<128,128,32,4,4,false,false,false,false,false><<<dim3(gG,1,1), 512>>>(
        N, 128, 128, 128, pTM, 128, gc2w, 128, pU1, 128, nullptr, nullptr);
    k_l2nl<<<nwBlocks, 256>>>(N);
    // SpMM #2 with fused EL -> X2
    k_csrmm<2><<<nwBlocks, 256>>>(pT2, pX2, nullptr, N);
    // readout: P = X2[bidx] @ wgt  (gather fused into GEMM A-load; no G buffer)
    int MP = B * L;                               // 204800
    mmgemm<128,64,32,4,2,false,false,false,false,true><<<dim3((MP + 127) / 128, 1, 1), 256>>>(
        MP, 64, 128, 128, pX2, 128, wgt, 64, pP, 64, nullptr, bidx);
    // H rows + appended sum row (relu applied here)
    k_hsum<<<B, 64>>>(B, L);
    // OUT = H @ lin1_w^T, split-K (8) atomic into d_out+1
    k_zero<<<1024, 256>>>(out, out_size);
    int KD = (L + 1) * 64;
    int kChunk = 416;                             // 13 BK-tiles; 8 splits
    int zs = (KD + kChunk - 1) / kChunk;
    mmgemm<128,128,32,4,4,true,false,false,true,false><<<dim3((B + 127) / 128, 1, zs), 512>>>(
        B, 128, KD, kChunk, pH, KD, lin1w, KD, out + 1, 128, nullptr, nullptr);
    k_addbias<<<(B * 128 + 255) / 256, 256>>>(out + 1, lin1b, B * 128);
    // loss + finalize
    k_loss<<<(B + 7) / 8, 256>>>(out + 1, cls, clsb, blab, B);
    k_final<<<1, 1>>>(out, out_size, B);
}

// round 11
// speedup vs baseline: 1.2160x; 1.0700x over previous
#include <cuda_runtime.h>
#include <cuda_bf16.h>
#include <cstdint>
#include <math.h>

// ---------------- problem-size constants (from reference) ----------------
#define NMAXN 100000
#define EMAXE 1600000
#define BMAXB 4096
#define LP1   51

#define EPSF 1e-7f
#define MINN 1e-15f
#define MAXN 1e6f

// ---------------- device scratch (static: no allocations allowed) --------
__device__ float g_scale[NMAXN];
__device__ float g_U1[NMAXN * 128];
__device__ float g_U2[NMAXN * 128];
__device__ float g_TA[NMAXN * 128];
__device__ float g_T1[NMAXN * 128];
__device__ float g_TM[NMAXN * 128];
__device__ float g_T2[NMAXN * 128];
__device__ float g_X2[NMAXN * 128];
__device__ float g_P [BMAXB * (LP1 - 1) * 64];
__device__ float g_H [BMAXB * LP1 * 64];
__device__ float g_ub[3][128];
__device__ float g_cp[3];        // c, K=1/c, sqrtK
__device__ float g_loss;
// CSR scratch
__device__ int   g_cnt[NMAXN];
__device__ int   g_off[NMAXN + 1];
__device__ int   g_cur[NMAXN];
__device__ int   g_ccol[EMAXE];
__device__ float g_cval[EMAXE];
__device__ int   g_bsum[512];

// ---------------- small device helpers ----------------
__device__ __forceinline__ float wsum(float v) {
#pragma unroll
    for (int o = 16; o; o >>= 1) v += __shfl_xor_sync(0xffffffffu, v, o);
    return v;
}

__device__ __forceinline__ float f_arcosh(float x) {
    x = fmaxf(x, 1.0f + EPSF);
    return logf(x + sqrtf(x * x - 1.0f));
}

__device__ __forceinline__ void d_EL(float* u, float sqrtK, float Kc) {
    float sq = wsum(u[0]*u[0] + u[1]*u[1] + u[2]*u[2] + u[3]*u[3]);
    float xn = fmaxf(sqrtf(sq), MINN);
    float th = xn / sqrtK;
    float coef = sqrtK * sinhf(th) / xn;
    u[0] *= coef; u[1] *= coef; u[2] *= coef; u[3] *= coef;
    float rs = wsum(u[0]*u[0] + u[1]*u[1] + u[2]*u[2] + u[3]*u[3]);
    float x0 = sqrtf(Kc + rs);
    float yn = fmaxf(sqrtf(rs), MINN);
    float s = sqrtK * f_arcosh(x0 / sqrtK);
    float f = s / yn;
    u[0] *= f; u[1] *= f; u[2] *= f; u[3] *= f;
}

__device__ __forceinline__ void d_TBT(float* u, const float* ub, float sqrtK,
                                      float Kc, int lane) {
    float sq = wsum(u[0]*u[0] + u[1]*u[1] + u[2]*u[2] + u[3]*u[3]);
    float xn = fmaxf(sqrtf(sq), MINN);
    float th = xn / sqrtK;
    float coef = sqrtK * sinhf(th) / xn;
    float a0 = coef*u[0], a1 = coef*u[1], a2 = coef*u[2], a3 = coef*u[3];
    float sp2 = wsum(a0*a0 + a1*a1 + a2*a2 + a3*a3);
    float x0 = sqrtf(Kc + sp2);
    float yn = fmaxf(sqrtf(sp2), MINN);
    float y0 = a0/yn, y1 = a1/yn, y2 = a2/yn, y3 = a3/yn;
    float ub0 = ub[lane*4+0], ub1 = ub[lane*4+1], ub2 = ub[lane*4+2], ub3 = ub[lane*4+3];
    float alpha = wsum(y0*ub0 + y1*ub1 + y2*ub2 + y3*ub3) / sqrtK;
    float c2 = alpha * (sqrtK - x0);
    float w0 = ub0 - c2*y0, w1 = ub1 - c2*y1, w2 = ub2 - c2*y2, w3 = ub3 - c2*y3;
    float wt = wsum(a0*w0 + a1*w1 + a2*w2 + a3*w3) / fmaxf(x0, EPSF);
    float md = wsum(w0*w0 + w1*w1 + w2*w2 + w3*w3) - wt*wt;
    float normu = sqrtf(fmaxf(md, EPSF));
    normu = fminf(normu, MAXN);
    float th2 = fmaxf(normu / sqrtK, MINN);
    float ch = coshf(th2);
    float sh = sinhf(th2) / th2;
    float r0 = ch*a0 + sh*w0, r1 = ch*a1 + sh*w1, r2 = ch*a2 + sh*w2, r3 = ch*a3 + sh*w3;
    float rs2 = wsum(r0*r0 + r1*r1 + r2*r2 + r3*r3);
    float x0n = sqrtf(Kc + rs2);
    float yn2 = fmaxf(sqrtf(rs2), MINN);
    float s = sqrtK * f_arcosh(x0n / sqrtK);
    float f = s / yn2;
    u[0] = f*r0; u[1] = f*r1; u[2] = f*r2; u[3] = f*r3;
}

// ---------------- elementwise / graph kernels ----------------

__global__ void k_init(const float* __restrict__ rawc,
                       const float* __restrict__ b0,
                       const float* __restrict__ b1,
                       const float* __restrict__ b2) {
    int lane = threadIdx.x;
    float rc = rawc[0];
    float c = fmaxf(rc, 0.f) + log1pf(expf(-fabsf(rc))) + 1e-5f;
    float Kc = 1.f / c;
    float sqrtK = sqrtf(Kc);
    if (lane == 0) { g_cp[0] = c; g_cp[1] = Kc; g_cp[2] = sqrtK; g_loss = 0.f; }
    const float* bs[3] = {b0, b1, b2};
#pragma unroll
    for (int k = 0; k < 3; k++) {
        float u[4];
#pragma unroll
        for (int i = 0; i < 4; i++) u[i] = bs[k][lane*4 + i];
        if (lane == 0) u[0] = 0.f;
        d_EL(u, sqrtK, Kc);
#pragma unroll
        for (int i = 0; i < 4; i++) g_ub[k][lane*4 + i] = u[i];
    }
}

__global__ void k_scale(const float* __restrict__ A1, int N) {
    int w = (blockIdx.x * blockDim.x + threadIdx.x) >> 5;
    if (w >= N) return;
    int lane = threadIdx.x & 31;
    float sqrtK = g_cp[2];
    const float4 v = *((const float4*)(A1 + (size_t)w * 128) + lane);
    float s4 = v.x*v.x + v.y*v.y + v.z*v.z + v.w*v.w;
    if (lane == 0) s4 -= v.x*v.x;
    float sq = wsum(s4);
    if (lane == 0) {
        float yn = fmaxf(sqrtf(sq), MINN);
        float s = sqrtK * f_arcosh(__ldg(A1 + (size_t)w * 128) / sqrtK);
        g_scale[w] = s / yn;
    }
}

__global__ void k_l1nl(int N) {
    int w = (blockIdx.x * blockDim.x + threadIdx.x) >> 5;
    if (w >= N) return;
    int lane = threadIdx.x & 31;
    float sqrtK = g_cp[2], Kc = g_cp[1];
    float u[4];
    float4 v = *((const float4*)(g_U1 + (size_t)w * 128) + lane);
    u[0]=v.x; u[1]=v.y; u[2]=v.z; u[3]=v.w; if (lane==0) u[0]=0.f;
    d_TBT(u, g_ub[0], sqrtK, Kc, lane);
    *((float4*)(g_TA + (size_t)w * 128) + lane) = make_float4(u[0],u[1],u[2],u[3]);
    v = *((const float4*)(g_U2 + (size_t)w * 128) + lane);
    u[0]=v.x; u[1]=v.y; u[2]=v.z; u[3]=v.w; if (lane==0) u[0]=0.f;
    d_TBT(u, g_ub[1], sqrtK, Kc, lane);
    *((float4*)(g_T1 + (size_t)w * 128) + lane) = make_float4(u[0],u[1],u[2],u[3]);
}

__global__ void k_l2nl(int N) {
    int w = (blockIdx.x * blockDim.x + threadIdx.x) >> 5;
    if (w >= N) return;
    int lane = threadIdx.x & 31;
    float sqrtK = g_cp[2], Kc = g_cp[1];
    float u[4];
    float4 v = *((const float4*)(g_U1 + (size_t)w * 128) + lane);
    u[0]=v.x; u[1]=v.y; u[2]=v.z; u[3]=v.w; if (lane==0) u[0]=0.f;
    d_TBT(u, g_ub[2], sqrtK, Kc, lane);
    *((float4*)(g_T2 + (size_t)w * 128) + lane) = make_float4(u[0],u[1],u[2],u[3]);
}

__global__ void k_zero(float* __restrict__ p, int n) {
    int i = blockIdx.x * blockDim.x + threadIdx.x;
    int st = gridDim.x * blockDim.x;
    for (; i < n; i += st) p[i] = 0.f;
}

// ---------------- CSR build ----------------
__global__ void k_zcnt(int N) {
    int i = blockIdx.x * blockDim.x + threadIdx.x;
    if (i < N) g_cnt[i] = 0;
}
__global__ void k_hist(const int* __restrict__ rows, int E) {
    int e = blockIdx.x * blockDim.x + threadIdx.x;
    if (e < E) atomicAdd(&g_cnt[__ldg(rows + e)], 1);
}
__global__ void k_scan1(int N) {
    __shared__ int sh[256];
    int b = blockIdx.x, t = threadIdx.x;
    int idx = b * 256 + t;
    int v = (idx < N) ? g_cnt[idx] : 0;
    sh[t] = v;
    __syncthreads();
    for (int o = 1; o < 256; o <<= 1) {
        int x = (t >= o) ? sh[t - o] : 0;
        __syncthreads();
        sh[t] += x;
        __syncthreads();
    }
    if (idx < N) g_off[idx] = sh[t] - v;
    if (t == 255) g_bsum[b] = sh[255];
}
__global__ void k_scan2(int nb) {
    __shared__ int sh[512];
    int t = threadIdx.x;
    int v = (t < nb) ? g_bsum[t] : 0;
    sh[t] = v;
    __syncthreads();
    for (int o = 1; o < 512; o <<= 1) {
        int x = (t >= o) ? sh[t - o] : 0;
        __syncthreads();
        sh[t] += x;
        __syncthreads();
    }
    if (t < nb) g_bsum[t] = sh[t] - v;
}
__global__ void k_scan3(int N, int E) {
    int i = blockIdx.x * blockDim.x + threadIdx.x;
    if (i < N) {
        int o = g_off[i] + g_bsum[i >> 8];
        g_off[i] = o;
        g_cur[i] = o;
    }
    if (i == 0) g_off[N] = E;
}
__global__ void k_scatter(const int* __restrict__ rows, const int* __restrict__ cols,
                          const float* __restrict__ vals, int E) {
    int e = blockIdx.x * blockDim.x + threadIdx.x;
    if (e >= E) return;
    int r = __ldg(rows + e);
    int pos = atomicAdd(&g_cur[r], 1);
    g_ccol[pos] = __ldg(cols + e);
    g_cval[pos] = __ldg(vals + e);
}

// ---------------- CSR SpMM with fused nonlinearity ---------------------------
template<int FUSE>
__global__ void k_csrmm(const float* __restrict__ T, float* __restrict__ OUT,
                        const float* __restrict__ nvec, int N) {
    int w = (blockIdx.x * blockDim.x + threadIdx.x) >> 5;
    if (w >= N) return;
    int lane = threadIdx.x & 31;
    int e0 = __ldg(g_off + w);
    int e1 = __ldg(g_off + w + 1);
    float a[4] = {0.f, 0.f, 0.f, 0.f};
    int e = e0;
    for (; e + 2 <= e1; e += 2) {
        int c0 = __ldg(g_ccol + e);
        int c1 = __ldg(g_ccol + e + 1);
        float v0 = __ldg(g_cval + e);
        float v1 = __ldg(g_cval + e + 1);
        float4 t0 = __ldg((const float4*)(T + (size_t)c0 * 128) + lane);
        float4 t1 = __ldg((const float4*)(T + (size_t)c1 * 128) + lane);
        a[0] += t0.x * v0 + t1.x * v1;
        a[1] += t0.y * v0 + t1.y * v1;
        a[2] += t0.z * v0 + t1.z * v1;
        a[3] += t0.w * v0 + t1.w * v1;
    }
    if (e < e1) {
        int c0 = __ldg(g_ccol + e);
        float v0 = __ldg(g_cval + e);
        float4 t0 = __ldg((const float4*)(T + (size_t)c0 * 128) + lane);
        a[0] += t0.x * v0; a[1] += t0.y * v0; a[2] += t0.z * v0; a[3] += t0.w * v0;
    }
    float sqrtK = g_cp[2], Kc = g_cp[1];
    if (FUSE == 1) {
        d_EL(a, sqrtK, Kc);
        float nv = __ldg(nvec + w);
        float om = 1.f - nv;
#pragma unroll
        for (int i = 0; i < 4; i++) a[i] *= om;
        d_EL(a, sqrtK, Kc);
        float b[4];
        float4 v = *((const float4*)(g_TA + (size_t)w * 128) + lane);
        b[0]=v.x*nv; b[1]=v.y*nv; b[2]=v.z*nv; b[3]=v.w*nv;
        d_EL(b, sqrtK, Kc);
#pragma unroll
        for (int i = 0; i < 4; i++) a[i] += b[i];
        d_EL(a, sqrtK, Kc);
    } else if (FUSE == 2) {
        d_EL(a, sqrtK, Kc);
    }
    *((float4*)(OUT + (size_t)w * 128) + lane) = make_float4(a[0], a[1], a[2], a[3]);
}

// H rows b*51+l = relu(P[b*50+l]); H row b*51+50 = relu(sum_l P[b*50+l])
__global__ void k_hsum(int B, int L) {
    int b = blockIdx.x;
    int j = threadIdx.x;            // 64 threads
    const float* Pb = g_P + (size_t)b * L * 64;
    float* Hb = g_H + (size_t)b * (L + 1) * 64;
    float s = 0.f;
    for (int l = 0; l < L; l++) {
        float p = Pb[(size_t)l * 64 + j];
        s += p;
        Hb[(size_t)l * 64 + j] = fmaxf(p, 0.f);
    }
    Hb[(size_t)L * 64 + j] = fmaxf(s, 0.f);
}

__global__ void k_addbias(float* __restrict__ o, const float* __restrict__ bias, int n) {
    int i = blockIdx.x * blockDim.x + threadIdx.x;
    if (i < n) o[i] += __ldg(bias + (i & 127));
}

__global__ void k_loss(const float* __restrict__ sel, const float* __restrict__ cls,
                       const float* __restrict__ cb, const int* __restrict__ lab, int B) {
    int b = (blockIdx.x * blockDim.x + threadIdx.x) >> 5;
    if (b >= B) return;
    int lane = threadIdx.x & 31;
    const float* row = sel + (size_t)b * 128;
    float d0 = 0.f, d1 = 0.f;
#pragma unroll
    for (int i = 0; i < 4; i++) {
        int d = lane * 4 + i;
        float o = row[d];
        d0 += o * __ldg(cls + d * 2 + 0);
        d1 += o * __ldg(cls + d * 2 + 1);
    }
    d0 = wsum(d0); d1 = wsum(d1);
    if (lane == 0) {
        float p0 = d0 + __ldg(cb + 0);
        float p1 = d1 + __ldg(cb + 1);
        float m = fmaxf(p0, p1);
        float lse = m + logf(expf(p0 - m) + expf(p1 - m));
        int y = __ldg(lab + b);
        float lp = (y == 0 ? p0 : p1) - lse;
        atomicAdd(&g_loss, lp);
    }
}

__global__ void k_final(float* __restrict__ out, int out_size, int B) {
    out[0] = -g_loss / (float)B;
    out[out_size - 1] = g_cp[0];
}

// ---------------- mma.sync helpers ----------------
__device__ __forceinline__ void ldm_x4(uint32_t* r, uint32_t addr) {
    asm volatile("ldmatrix.sync.aligned.m8n8.x4.shared.b16 {%0,%1,%2,%3}, [%4];"
        : "=r"(r[0]), "=r"(r[1]), "=r"(r[2]), "=r"(r[3]) : "r"(addr));
}
__device__ __forceinline__ void mma_bf16(float* c, const uint32_t* a, const uint32_t* b) {
    asm volatile("mma.sync.aligned.m16n8k16.row.col.f32.bf16.bf16.f32 "
        "{%0,%1,%2,%3}, {%4,%5,%6,%7}, {%8,%9}, {%0,%1,%2,%3};"
        : "+f"(c[0]), "+f"(c[1]), "+f"(c[2]), "+f"(c[3])
        : "r"(a[0]), "r"(a[1]), "r"(a[2]), "r"(a[3]), "r"(b[0]), "r"(b[1]));
}
__device__ __forceinline__ uint32_t pack_hi2(float x, float y) {
    __nv_bfloat16 hx = __float2bfloat16(x), hy = __float2bfloat16(y);
    return ((uint32_t)__bfloat16_as_ushort(hy) << 16) | __bfloat16_as_ushort(hx);
}
__device__ __forceinline__ uint32_t pack_lo2(float x, float y) {
    __nv_bfloat16 hx = __float2bfloat16(x), hy = __float2bfloat16(y);
    __nv_bfloat16 lx = __float2bfloat16(x - __bfloat162float(hx));
    __nv_bfloat16 ly = __float2bfloat16(y - __bfloat162float(hy));
    return ((uint32_t)__bfloat16_as_ushort(ly) << 16) | __bfloat16_as_ushort(lx);
}
__device__ __forceinline__ void packhl(float x, float y, uint32_t& hi, uint32_t& lo) {
    __nv_bfloat16 hx = __float2bfloat16(x), hy = __float2bfloat16(y);
    hi = ((uint32_t)__bfloat16_as_ushort(hy) << 16) | __bfloat16_as_ushort(hx);
    __nv_bfloat16 lx = __float2bfloat16(x - __bfloat162float(hx));
    __nv_bfloat16 ly = __float2bfloat16(y - __bfloat162float(hy));
    lo = ((uint32_t)__bfloat16_as_ushort(ly) << 16) | __bfloat16_as_ushort(lx);
}
__device__ __forceinline__ void cp16(uint32_t dst, const void* src, bool valid) {
    int sz = valid ? 16 : 0;
    asm volatile("cp.async.cg.shared.global [%0], [%1], 16, %2;"
                 :: "r"(dst), "l"(src), "r"(sz) : "memory");
}
#define CP_COMMIT() asm volatile("cp.async.commit_group;" ::: "memory")
#define CP_WAIT(n)  asm volatile("cp.async.wait_group %0;" :: "n"(n) : "memory")

// ---------------- cp.async-pipelined GEMM (K=128, BM=BN=128, 512 thr) --------
// C_p = (diag(scale)*A')@B_p (ASCALE: col0 zeroed); fp32 staged, fragments built
// in registers per mma.sync m16n8k16 spec; 4 stages cover all of K.
#define PLALD 36
#define PLBLD 132
#define PLASTG (128 * PLALD)
#define PLBSTG (32 * PLBLD)
#define PL_SMEM ((4 * PLASTG + 4 * PLBSTG) * 4)
template<int NPASS, bool ASCALE>
__global__ void __launch_bounds__(512)
mmgemm_pl(int M, const float* __restrict__ A, const float* __restrict__ scale,
          const float* __restrict__ B0, const float* __restrict__ B1,
          float* __restrict__ C0, float* __restrict__ C1) {
    extern __shared__ __align__(16) float psm[];
    float* Asm = psm;
    float* Bsm = psm + 4 * PLASTG;

    int tid = threadIdx.x, lane = tid & 31, wid = tid >> 5;
    int wm = wid >> 2, wn = wid & 3;
    int m0 = blockIdx.x * 128;
    uint32_t sbase = (uint32_t)__cvta_generic_to_shared(psm);

    float sc[2][2];
    if (ASCALE) {
#pragma unroll
        for (int mt = 0; mt < 2; mt++) {
            int r0 = m0 + wm * 32 + mt * 16 + (lane >> 2);
            sc[mt][0] = (r0 < M) ? __ldg(scale + r0) : 0.f;
            sc[mt][1] = (r0 + 8 < M) ? __ldg(scale + r0 + 8) : 0.f;
        }
    }

    auto issueA = [&](int t) {
#pragma unroll
        for (int cc = 0; cc < 2; cc++) {
            int c = tid + cc * 512;
            int row = c >> 3, q = c & 7;
            uint32_t dst = sbase + (uint32_t)((t * PLASTG + row * PLALD + q * 4) * 4);
            const float* src = A + (size_t)(m0 + row) * 128 + t * 32 + q * 4;
            cp16(dst, src, (m0 + row) < M);
        }
    };
    auto issueB = [&](const float* Bg, int t) {
#pragma unroll
        for (int cc = 0; cc < 2; cc++) {
            int c = tid + cc * 512;
            int kr = c >> 5, q = c & 31;
            uint32_t dst = sbase + (uint32_t)((4 * PLASTG + t * PLBSTG + kr * PLBLD + q * 4) * 4);
            const float* src = Bg + (size_t)(t * 32 + kr) * 128 + q * 4;
            cp16(dst, src, true);
        }
    };

#pragma unroll
    for (int t = 0; t < 4; t++) { issueA(t); issueB(B0, t); CP_COMMIT(); }

    float acc[2][4][4];
    int kbl = (lane & 3) * 2;
    int rlo = lane >> 2;

#pragma unroll
    for (int pass = 0; pass < NPASS; pass++) {
#pragma unroll
        for (int i = 0; i < 2; i++)
#pragma unroll
            for (int j = 0; j < 4; j++)
#pragma unroll
                for (int q = 0; q < 4; q++) acc[i][j][q] = 0.f;

#pragma unroll
        for (int t = 0; t < 4; t++) {
            if (t == 0) CP_WAIT(3);
            else if (t == 1) CP_WAIT(2);
            else if (t == 2) CP_WAIT(1);
            else CP_WAIT(0);
            __syncthreads();
            const float* At = Asm + t * PLASTG;
            const float* Bt = Bsm + t * PLBSTG;
#pragma unroll
            for (int kk = 0; kk < 32; kk += 16) {
                int kb = kk + kbl;
                uint32_t ah[2][4], al[2][4], bh[2][4], bl[2][4];
#pragma unroll
                for (int mt = 0; mt < 2; mt++) {
                    const float* pr0 = At + (wm * 32 + mt * 16 + rlo) * PLALD;
                    const float* pr1 = pr0 + 8 * PLALD;
                    float f00 = pr0[kb], f01 = pr0[kb+1], f08 = pr0[kb+8], f09 = pr0[kb+9];
                    float f10 = pr1[kb], f11 = pr1[kb+1], f18 = pr1[kb+8], f19 = pr1[kb+9];
                    if (ASCALE) {
                        float s0 = sc[mt][0], s1 = sc[mt][1];
                        f00 *= s0; f01 *= s0; f08 *= s0; f09 *= s0;
                        f10 *= s1; f11 *= s1; f18 *= s1; f19 *= s1;
                        if (t == 0 && kb == 0) { f00 = 0.f; f10 = 0.f; }
                    }
                    packhl(f00, f01, ah[mt][0], al[mt][0]);
                    packhl(f10, f11, ah[mt][1], al[mt][1]);
                    packhl(f08, f09, ah[mt][2], al[mt][2]);
                    packhl(f18, f19, ah[mt][3], al[mt][3]);
                }
#pragma unroll
                for (int np = 0; np < 2; np++) {
#pragma unroll
                    for (int h = 0; h < 2; h++) {
                        int nB = wn * 32 + np * 16 + h * 8 + rlo;
                        float g0 = Bt[(kb)     * PLBLD + nB];
                        float g1 = Bt[(kb + 1) * PLBLD + nB];
                        float g8 = Bt[(kb + 8) * PLBLD + nB];
                        float g9 = Bt[(kb + 9) * PLBLD + nB];
                        packhl(g0, g1, bh[np][h*2+0], bl[np][h*2+0]);
                        packhl(g8, g9, bh[np][h*2+1], bl[np][h*2+1]);
                    }
                }
#pragma unroll
                for (int np = 0; np < 2; np++)
#pragma unroll
                    for (int mt = 0; mt < 2; mt++) {
                        mma_bf16(acc[mt][2*np],   ah[mt], bh[np]);
                        mma_bf16(acc[mt][2*np+1], ah[mt], bh[np] + 2);
                    }
#pragma unroll
                for (int np = 0; np < 2; np++)
#pragma unroll
                    for (int mt = 0; mt < 2; mt++) {
                        mma_bf16(acc[mt][2*np],   ah[mt], bl[np]);
                        mma_bf16(acc[mt][2*np+1], ah[mt], bl[np] + 2);
                    }
#pragma unroll
                for (int np = 0; np < 2; np++)
#pragma unroll
                    for (int mt = 0; mt < 2; mt++) {
                        mma_bf16(acc[mt][2*np],   al[mt], bh[np]);
                        mma_bf16(acc[mt][2*np+1], al[mt], bh[np] + 2);
                    }
            }
        }

        // epilogue
        float* Cg = pass ? C1 : C0;
#pragma unroll
        for (int mt = 0; mt < 2; mt++) {
            int row0 = m0 + wm * 32 + mt * 16 + rlo;
            int row1 = row0 + 8;
#pragma unroll
            for (int nt = 0; nt < 4; nt++) {
                int col = wn * 32 + nt * 8 + (lane & 3) * 2;
                if (row0 < M)
                    *reinterpret_cast<float2*>(Cg + (size_t)row0 * 128 + col) =
                        make_float2(acc[mt][nt][0], acc[mt][nt][1]);
                if (row1 < M)
                    *reinterpret_cast<float2*>(Cg + (size_t)row1 * 128 + col) =
                        make_float2(acc[mt][nt][2], acc[mt][nt][3]);
            }
        }
        if (pass + 1 < NPASS) {
            __syncthreads();   // all Bsm reads done before refill
#pragma unroll
            for (int t = 0; t < 4; t++) { issueB(B1, t); CP_COMMIT(); }
        }
    }
}

// ---------------- general mma.sync GEMM (register-prefetch; readout path) ----
template<int BM, int BN, int BK, int NWM, int NWN, bool BT, bool RELU, bool ASCALE,
         bool ATOMIC, bool GATHER>
__global__ void __launch_bounds__(NWM * NWN * 32)
mmgemm(int M, int N, int K, int kChunk,
       const float* __restrict__ A, int lda,
       const float* __restrict__ B, int ldb,
       float* __restrict__ C, int ldc,
       const float* __restrict__ scale, const int* __restrict__ gidx) {
    constexpr int THREADS = NWM * NWN * 32;
    constexpr int WM = BM / NWM;
    constexpr int WN = BN / NWN;
    constexpr int MT = WM / 16;
    constexpr int NT = WN / 8;
    constexpr int NP = NT / 2;
    constexpr int LDK = BK + 8;
    constexpr int NA = (BM * (BK / 4) + THREADS - 1) / THREADS;
    constexpr int NBCNT = BT ? BN * (BK / 4) : BK * (BN / 4);
    constexpr int NB = (NBCNT + THREADS - 1) / THREADS;

    __shared__ __align__(16) __nv_bfloat16 AsH[BM * LDK];
    __shared__ __align__(16) __nv_bfloat16 AsL[BM * LDK];
    __shared__ __align__(16) __nv_bfloat16 BsH[BN * LDK];
    __shared__ __align__(16) __nv_bfloat16 BsL[BN * LDK];

    int tid = threadIdx.x;
    int lane = tid & 31;
    int wid = tid >> 5;
    int wm = wid / NWN;
    int wn = wid % NWN;
    int m0 = blockIdx.x * BM;
    int n0 = blockIdx.y * BN;
    int kStart = blockIdx.z * kChunk;
    int kEnd = min(K, kStart + kChunk);

    float acc[MT][NT][4];
#pragma unroll
    for (int i = 0; i < MT; i++)
#pragma unroll
        for (int j = 0; j < NT; j++)
#pragma unroll
            for (int q = 0; q < 4; q++) acc[i][j][q] = 0.f;

    float4 pa[NA]; float ps[NA]; float4 pb[NB];

    auto loadA = [&](int k0) {
#pragma unroll
        for (int t = 0; t < NA; t++) {
            int i = tid + t * THREADS;
            float4 v = make_float4(0.f, 0.f, 0.f, 0.f);
            float s = 0.f;
            if (i < BM * (BK / 4)) {
                int r = i / (BK / 4);
                int kc = (i % (BK / 4)) * 4;
                int gr = m0 + r;
                if (gr < M) {
                    size_t ar = GATHER ? (size_t)__ldg(gidx + gr) : (size_t)gr;
                    v = *reinterpret_cast<const float4*>(A + ar * lda + k0 + kc);
                    if (ASCALE) s = __ldg(scale + gr);
                }
            }
            pa[t] = v;
            if (ASCALE) ps[t] = s;
        }
    };
    auto storeA = [&](int k0) {
#pragma unroll
        for (int t = 0; t < NA; t++) {
            int i = tid + t * THREADS;
            if (i < BM * (BK / 4)) {
                int r = i / (BK / 4);
                int kc = (i % (BK / 4)) * 4;
                float4 v = pa[t];
                if (ASCALE) {
                    float s = ps[t];
                    v.x *= s; v.y *= s; v.z *= s; v.w *= s;
                    if (k0 + kc == 0) v.x = 0.f;
                }
                *(uint32_t*)&AsH[r * LDK + kc]     = pack_hi2(v.x, v.y);
                *(uint32_t*)&AsH[r * LDK + kc + 2] = pack_hi2(v.z, v.w);
                *(uint32_t*)&AsL[r * LDK + kc]     = pack_lo2(v.x, v.y);
                *(uint32_t*)&AsL[r * LDK + kc + 2] = pack_lo2(v.z, v.w);
            }
        }
    };
    auto loadB = [&](int k0) {
#pragma unroll
        for (int t = 0; t < NB; t++) {
            int i = tid + t * THREADS;
            float4 v = make_float4(0.f, 0.f, 0.f, 0.f);
            if (i < NBCNT) {
                if (BT) {
                    int r = i / (BK / 4);
                    int kc = (i % (BK / 4)) * 4;
                    v = *reinterpret_cast<const float4*>(B + (size_t)(n0 + r) * ldb + k0 + kc);
                } else {
                    int kk = i / (BN / 4);
                    int nc = (i % (BN / 4)) * 4;
                    v = *reinterpret_cast<const float4*>(B + (size_t)(k0 + kk) * ldb + n0 + nc);
                }
            }
            pb[t] = v;
        }
    };
    auto storeB = [&]() {
#pragma unroll
        for (int t = 0; t < NB; t++) {
            int i = tid + t * THREADS;
            if (i < NBCNT) {
                float4 v = pb[t];
                if (BT) {
                    int r = i / (BK / 4);
                    int kc = (i % (BK / 4)) * 4;
                    *(uint32_t*)&BsH[r * LDK + kc]     = pack_hi2(v.x, v.y);
                    *(uint32_t*)&BsH[r * LDK + kc + 2] = pack_hi2(v.z, v.w);
                    *(uint32_t*)&BsL[r * LDK + kc]     = pack_lo2(v.x, v.y);
                    *(uint32_t*)&BsL[r * LDK + kc + 2] = pack_lo2(v.z, v.w);
                } else {
                    int kk = i / (BN / 4);
                    int nc = (i % (BN / 4)) * 4;
                    float vv[4] = {v.x, v.y, v.z, v.w};
#pragma unroll
                    for (int j = 0; j < 4; j++) {
                        __nv_bfloat16 h = __float2bfloat16(vv[j]);
                        BsH[(nc + j) * LDK + kk] = h;
                        BsL[(nc + j) * LDK + kk] = __float2bfloat16(vv[j] - __bfloat162float(h));
                    }
                }
            }
        }
    };

    int a_row = (lane & 7) + ((lane >> 3) & 1) * 8;
    int a_kof = (lane >> 4) * 8;
    int b_row = (lane & 7) + (lane >> 4) * 8;
    int b_kof = ((lane >> 3) & 1) * 8;

    loadA(kStart);
    loadB(kStart);

    for (int k0 = kStart; k0 < kEnd; k0 += BK) {
        storeA(k0);
        storeB();
        __syncthreads();
        if (k0 + BK < kEnd) {
            loadA(k0 + BK);
            loadB(k0 + BK);
        }
#pragma unroll
        for (int kk = 0; kk < BK; kk += 16) {
            uint32_t ah[MT][4], al[MT][4], bh[NP][4], bl[NP][4];
#pragma unroll
            for (int mt = 0; mt < MT; mt++) {
                int row = wm * WM + mt * 16 + a_row;
                int col = kk + a_kof;
                ldm_x4(ah[mt], (uint32_t)__cvta_generic_to_shared(&AsH[row * LDK + col]));
                ldm_x4(al[mt], (uint32_t)__cvta_generic_to_shared(&AsL[row * LDK + col]));
            }
#pragma unroll
            for (int np = 0; np < NP; np++) {
                int nrow = wn * WN + np * 16 + b_row;
                int col = kk + b_kof;
                ldm_x4(bh[np], (uint32_t)__cvta_generic_to_shared(&BsH[nrow * LDK + col]));
                ldm_x4(bl[np], (uint32_t)__cvta_generic_to_shared(&BsL[nrow * LDK + col]));
            }
#pragma unroll
            for (int np = 0; np < NP; np++)
#pragma unroll
                for (int mt = 0; mt < MT; mt++) {
                    mma_bf16(acc[mt][2*np],   ah[mt], bh[np]);
                    mma_bf16(acc[mt][2*np+1], ah[mt], bh[np] + 2);
                }
#pragma unroll
            for (int np = 0; np < NP; np++)
#pragma unroll
                for (int mt = 0; mt < MT; mt++) {
                    mma_bf16(acc[mt][2*np],   ah[mt], bl[np]);
                    mma_bf16(acc[mt][2*np+1], ah[mt], bl[np] + 2);
                }
#pragma unroll
            for (int np = 0; np < NP; np++)
#pragma unroll
                for (int mt = 0; mt < MT; mt++) {
                    mma_bf16(acc[mt][2*np],   al[mt], bh[np]);
                    mma_bf16(acc[mt][2*np+1], al[mt], bh[np] + 2);
                }
        }
        __syncthreads();
    }

#pragma unroll
    for (int mt = 0; mt < MT; mt++) {
        int row0 = m0 + wm * WM + mt * 16 + (lane >> 2);
        int row1 = row0 + 8;
#pragma unroll
        for (int nt = 0; nt < NT; nt++) {
            int col = n0 + wn * WN + nt * 8 + (lane & 3) * 2;
            float c0 = acc[mt][nt][0], c1 = acc[mt][nt][1];
            float c2 = acc[mt][nt][2], c3 = acc[mt][nt][3];
            if (RELU) {
                c0 = fmaxf(c0, 0.f); c1 = fmaxf(c1, 0.f);
                c2 = fmaxf(c2, 0.f); c3 = fmaxf(c3, 0.f);
            }
            if (ATOMIC) {
                if (row0 < M) {
                    atomicAdd(C + (size_t)row0 * ldc + col,     c0);
                    atomicAdd(C + (size_t)row0 * ldc + col + 1, c1);
                }
                if (row1 < M) {
                    atomicAdd(C + (size_t)row1 * ldc + col,     c2);
                    atomicAdd(C + (size_t)row1 * ldc + col + 1, c3);
                }
            } else {
                if (row0 < M)
                    *reinterpret_cast<float2*>(C + (size_t)row0 * ldc + col) = make_float2(c0, c1);
                if (row1 < M)
                    *reinterpret_cast<float2*>(C + (size_t)row1 * ldc + col) = make_float2(c2, c3);
            }
        }
    }
}

// ---------------- host ----------------
extern "C" void kernel_launch(void* const* d_in, const int* in_sizes, int n_in,
                              void* d_out, int out_size) {
    const float* A1    = (const float*)d_in[0];
    const int*   rows  = (const int*)  d_in[1];
    const int*   cols  = (const int*)  d_in[2];
    const float* vals  = (const float*)d_in[3];
    const int*   bidx  = (const int*)  d_in[4];
    const int*   blab  = (const int*)  d_in[5];
    const float* rawc  = (const float*)d_in[6];
    const float* nvec  = (const float*)d_in[7];
    const float* Lin1  = (const float*)d_in[8];
    const float* Lin1b = (const float*)d_in[9];
    const float* gc1w  = (const float*)d_in[10];
    const float* gc1b  = (const float*)d_in[11];
    const float* gc2w  = (const float*)d_in[12];
    const float* gc2b  = (const float*)d_in[13];
    const float* wgt   = (const float*)d_in[14];
    const float* lin1w = (const float*)d_in[15];
    const float* lin1b = (const float*)d_in[16];
    const float* cls   = (const float*)d_in[17];
    const float* clsb  = (const float*)d_in[18];
    float* out = (float*)d_out;

    int N = in_sizes[0] / 128;
    int E = in_sizes[1];
    int B = in_sizes[5];
    int L = in_sizes[4] / B;

    float *pScale, *pU1, *pU2, *pTA, *pT1, *pTM, *pT2, *pX2, *pP, *pH;
    cudaGetSymbolAddress((void**)&pScale, g_scale);
    cudaGetSymbolAddress((void**)&pU1, g_U1);
    cudaGetSymbolAddress((void**)&pU2, g_U2);
    cudaGetSymbolAddress((void**)&pTA, g_TA);
    cudaGetSymbolAddress((void**)&pT1, g_T1);
    cudaGetSymbolAddress((void**)&pTM, g_TM);
    cudaGetSymbolAddress((void**)&pT2, g_T2);
    cudaGetSymbolAddress((void**)&pX2, g_X2);
    cudaGetSymbolAddress((void**)&pP,  g_P);
    cudaGetSymbolAddress((void**)&pH,  g_H);

    cudaFuncSetAttribute(mmgemm_pl<2, true>,
                         cudaFuncAttributeMaxDynamicSharedMemorySize, PL_SMEM);
    cudaFuncSetAttribute(mmgemm_pl<1, false>,
                         cudaFuncAttributeMaxDynamicSharedMemorySize, PL_SMEM);

    int nwBlocks = (N + 7) / 8;
    int gG = (N + 127) / 128;
    int nb = (N + 255) / 256;

    // constants + bias tangents
    k_init<<<1, 32>>>(rawc, Lin1b, gc1b, gc2b);
    // CSR build
    k_zcnt<<<(N + 255) / 256, 256>>>(N);
    k_hist<<<(E + 255) / 256, 256>>>(rows, E);
    k_scan1<<<nb, 256>>>(N);
    k_scan2<<<1, 512>>>(nb);
    k_scan3<<<(N + 255) / 256, 256>>>(N, E);
    k_scatter<<<(E + 255) / 256, 256>>>(rows, cols, vals, E);
    // logmap0 scaling of A1
    k_scale<<<nwBlocks, 256>>>(A1, N);
    // U1 = T0 @ Lin1 ; U2 = T0 @ gc1_w — cp.async-pipelined dual GEMM
    mmgemm_pl<2, true><<<gG, 512, PL_SMEM>>>(N, A1, pScale, Lin1, gc1w, pU1, pU2);
    // nonlinear: t_a1 (Lin1 path) and T1 (gc1 path)
    k_l1nl<<<nwBlocks, 256>>>(N);
    // SpMM #1 with fused mix -> TM
    k_csrmm<1><<<nwBlocks, 256>>>(pT1, pTM, nvec, N);
    // U3 = Tm @ gc2_w (into g_U1) — pipelined
    mmgemm_pl<1, false><<<gG, 512, PL_SMEM>>>(N, pTM, nullptr, gc2w, nullptr, pU1, nullptr);
    k_l2nl<<<nwBlocks, 256>>>(N);
    // SpMM #2 with fused EL -> X2
    k_csrmm<2><<<nwBlocks, 256>>>(pT2, pX2, nullptr, N);
    // readout: P = X2[bidx] @ wgt  (gather fused into GEMM A-load)
    int MP = B * L;
    mmgemm<128,64,32,4,2,false,false,false,false,true><<<dim3((MP + 127) / 128, 1, 1), 256>>>(
        MP, 64, 128, 128, pX2, 128, wgt, 64, pP, 64, nullptr, bidx);
    // H rows + appended sum row (relu applied here)
    k_hsum<<<B, 64>>>(B, L);
    // OUT = H @ lin1_w^T, split-K (8) atomic into d_out+1
    k_zero<<<1024, 256>>>(out, out_size);
    int KD = (L + 1) * 64;
    int kChunk = 416;
    int zs = (KD + kChunk - 1) / kChunk;
    mmgemm<128,128,32,4,4,true,false,false,true,false><<<dim3((B + 127) / 128, 1, zs), 512>>>(
        B, 128, KD, kChunk, pH, KD, lin1w, KD, out + 1, 128, nullptr, nullptr);
    k_addbias<<<(B * 128 + 255) / 256, 256>>>(out + 1, lin1b, B * 128);
    // loss + finalize
    k_loss<<<(B + 7) / 8, 256>>>(out + 1, cls, clsb, blab, B);
    k_final<<<1, 1>>>(out, out_size, B);
}

// round 12
// speedup vs baseline: 1.2688x; 1.0434x over previous
#include <cuda_runtime.h>
#include <cuda_bf16.h>
#include <cstdint>
#include <math.h>

// ---------------- problem-size constants (from reference) ----------------
#define NMAXN 100000
#define EMAXE 1600000
#define BMAXB 4096
#define LP1   51

#define EPSF 1e-7f
#define MINN 1e-15f
#define MAXN 1e6f

// ---------------- device scratch (static: no allocations allowed) --------
__device__ float g_scale[NMAXN];
__device__ float g_U1[NMAXN * 128];
__device__ float g_U2[NMAXN * 128];
__device__ float g_TA[NMAXN * 128];
__device__ float g_T1[NMAXN * 128];
__device__ float g_TM[NMAXN * 128];
__device__ float g_T2[NMAXN * 128];
__device__ float g_X2[NMAXN * 128];
__device__ float g_P [BMAXB * (LP1 - 1) * 64];
__device__ float g_H [BMAXB * LP1 * 64];
__device__ float g_ub[3][128];
__device__ float g_cp[3];        // c, K=1/c, sqrtK
__device__ float g_loss;
// CSR scratch
__device__ int   g_cnt[NMAXN];
__device__ int   g_off[NMAXN + 1];
__device__ int   g_cur[NMAXN];
__device__ int   g_ccol[EMAXE];
__device__ float g_cval[EMAXE];
__device__ int   g_bsum[512];

// ---------------- small device helpers ----------------
__device__ __forceinline__ float wsum(float v) {
#pragma unroll
    for (int o = 16; o; o >>= 1) v += __shfl_xor_sync(0xffffffffu, v, o);
    return v;
}

__device__ __forceinline__ float f_arcosh(float x) {
    x = fmaxf(x, 1.0f + EPSF);
    return logf(x + sqrtf(x * x - 1.0f));
}

__device__ __forceinline__ void d_EL(float* u, float sqrtK, float Kc) {
    float sq = wsum(u[0]*u[0] + u[1]*u[1] + u[2]*u[2] + u[3]*u[3]);
    float xn = fmaxf(sqrtf(sq), MINN);
    float th = xn / sqrtK;
    float coef = sqrtK * sinhf(th) / xn;
    u[0] *= coef; u[1] *= coef; u[2] *= coef; u[3] *= coef;
    float rs = wsum(u[0]*u[0] + u[1]*u[1] + u[2]*u[2] + u[3]*u[3]);
    float x0 = sqrtf(Kc + rs);
    float yn = fmaxf(sqrtf(rs), MINN);
    float s = sqrtK * f_arcosh(x0 / sqrtK);
    float f = s / yn;
    u[0] *= f; u[1] *= f; u[2] *= f; u[3] *= f;
}

__device__ __forceinline__ void d_TBT(float* u, const float* ub, float sqrtK,
                                      float Kc, int lane) {
    float sq = wsum(u[0]*u[0] + u[1]*u[1] + u[2]*u[2] + u[3]*u[3]);
    float xn = fmaxf(sqrtf(sq), MINN);
    float th = xn / sqrtK;
    float coef = sqrtK * sinhf(th) / xn;
    float a0 = coef*u[0], a1 = coef*u[1], a2 = coef*u[2], a3 = coef*u[3];
    float sp2 = wsum(a0*a0 + a1*a1 + a2*a2 + a3*a3);
    float x0 = sqrtf(Kc + sp2);
    float yn = fmaxf(sqrtf(sp2), MINN);
    float y0 = a0/yn, y1 = a1/yn, y2 = a2/yn, y3 = a3/yn;
    float ub0 = ub[lane*4+0], ub1 = ub[lane*4+1], ub2 = ub[lane*4+2], ub3 = ub[lane*4+3];
    float alpha = wsum(y0*ub0 + y1*ub1 + y2*ub2 + y3*ub3) / sqrtK;
    float c2 = alpha * (sqrtK - x0);
    float w0 = ub0 - c2*y0, w1 = ub1 - c2*y1, w2 = ub2 - c2*y2, w3 = ub3 - c2*y3;
    float wt = wsum(a0*w0 + a1*w1 + a2*w2 + a3*w3) / fmaxf(x0, EPSF);
    float md = wsum(w0*w0 + w1*w1 + w2*w2 + w3*w3) - wt*wt;
    float normu = sqrtf(fmaxf(md, EPSF));
    normu = fminf(normu, MAXN);
    float th2 = fmaxf(normu / sqrtK, MINN);
    float ch = coshf(th2);
    float sh = sinhf(th2) / th2;
    float r0 = ch*a0 + sh*w0, r1 = ch*a1 + sh*w1, r2 = ch*a2 + sh*w2, r3 = ch*a3 + sh*w3;
    float rs2 = wsum(r0*r0 + r1*r1 + r2*r2 + r3*r3);
    float x0n = sqrtf(Kc + rs2);
    float yn2 = fmaxf(sqrtf(rs2), MINN);
    float s = sqrtK * f_arcosh(x0n / sqrtK);
    float f = s / yn2;
    u[0] = f*r0; u[1] = f*r1; u[2] = f*r2; u[3] = f*r3;
}

// ---------------- elementwise / graph kernels ----------------

__global__ void k_init(const float* __restrict__ rawc,
                       const float* __restrict__ b0,
                       const float* __restrict__ b1,
                       const float* __restrict__ b2) {
    int lane = threadIdx.x;
    float rc = rawc[0];
    float c = fmaxf(rc, 0.f) + log1pf(expf(-fabsf(rc))) + 1e-5f;
    float Kc = 1.f / c;
    float sqrtK = sqrtf(Kc);
    if (lane == 0) { g_cp[0] = c; g_cp[1] = Kc; g_cp[2] = sqrtK; g_loss = 0.f; }
    const float* bs[3] = {b0, b1, b2};
#pragma unroll
    for (int k = 0; k < 3; k++) {
        float u[4];
#pragma unroll
        for (int i = 0; i < 4; i++) u[i] = bs[k][lane*4 + i];
        if (lane == 0) u[0] = 0.f;
        d_EL(u, sqrtK, Kc);
#pragma unroll
        for (int i = 0; i < 4; i++) g_ub[k][lane*4 + i] = u[i];
    }
}

__global__ void k_scale(const float* __restrict__ A1, int N) {
    int w = (blockIdx.x * blockDim.x + threadIdx.x) >> 5;
    if (w >= N) return;
    int lane = threadIdx.x & 31;
    float sqrtK = g_cp[2];
    const float4 v = *((const float4*)(A1 + (size_t)w * 128) + lane);
    float s4 = v.x*v.x + v.y*v.y + v.z*v.z + v.w*v.w;
    if (lane == 0) s4 -= v.x*v.x;
    float sq = wsum(s4);
    if (lane == 0) {
        float yn = fmaxf(sqrtf(sq), MINN);
        float s = sqrtK * f_arcosh(__ldg(A1 + (size_t)w * 128) / sqrtK);
        g_scale[w] = s / yn;
    }
}

__global__ void k_l1nl(int N) {
    int w = (blockIdx.x * blockDim.x + threadIdx.x) >> 5;
    if (w >= N) return;
    int lane = threadIdx.x & 31;
    float sqrtK = g_cp[2], Kc = g_cp[1];
    float u[4];
    float4 v = *((const float4*)(g_U1 + (size_t)w * 128) + lane);
    u[0]=v.x; u[1]=v.y; u[2]=v.z; u[3]=v.w; if (lane==0) u[0]=0.f;
    d_TBT(u, g_ub[0], sqrtK, Kc, lane);
    *((float4*)(g_TA + (size_t)w * 128) + lane) = make_float4(u[0],u[1],u[2],u[3]);
    v = *((const float4*)(g_U2 + (size_t)w * 128) + lane);
    u[0]=v.x; u[1]=v.y; u[2]=v.z; u[3]=v.w; if (lane==0) u[0]=0.f;
    d_TBT(u, g_ub[1], sqrtK, Kc, lane);
    *((float4*)(g_T1 + (size_t)w * 128) + lane) = make_float4(u[0],u[1],u[2],u[3]);
}

__global__ void k_l2nl(int N) {
    int w = (blockIdx.x * blockDim.x + threadIdx.x) >> 5;
    if (w >= N) return;
    int lane = threadIdx.x & 31;
    float sqrtK = g_cp[2], Kc = g_cp[1];
    float u[4];
    float4 v = *((const float4*)(g_U1 + (size_t)w * 128) + lane);
    u[0]=v.x; u[1]=v.y; u[2]=v.z; u[3]=v.w; if (lane==0) u[0]=0.f;
    d_TBT(u, g_ub[2], sqrtK, Kc, lane);
    *((float4*)(g_T2 + (size_t)w * 128) + lane) = make_float4(u[0],u[1],u[2],u[3]);
}

__global__ void k_zero(float* __restrict__ p, int n) {
    int i = blockIdx.x * blockDim.x + threadIdx.x;
    int st = gridDim.x * blockDim.x;
    for (; i < n; i += st) p[i] = 0.f;
}

// ---------------- CSR build ----------------
__global__ void k_zcnt(int N) {
    int i = blockIdx.x * blockDim.x + threadIdx.x;
    if (i < N) g_cnt[i] = 0;
}
__global__ void k_hist(const int* __restrict__ rows, int E) {
    int e = blockIdx.x * blockDim.x + threadIdx.x;
    if (e < E) atomicAdd(&g_cnt[__ldg(rows + e)], 1);
}
__global__ void k_scan1(int N) {
    __shared__ int sh[256];
    int b = blockIdx.x, t = threadIdx.x;
    int idx = b * 256 + t;
    int v = (idx < N) ? g_cnt[idx] : 0;
    sh[t] = v;
    __syncthreads();
    for (int o = 1; o < 256; o <<= 1) {
        int x = (t >= o) ? sh[t - o] : 0;
        __syncthreads();
        sh[t] += x;
        __syncthreads();
    }
    if (idx < N) g_off[idx] = sh[t] - v;
    if (t == 255) g_bsum[b] = sh[255];
}
__global__ void k_scan2(int nb) {
    __shared__ int sh[512];
    int t = threadIdx.x;
    int v = (t < nb) ? g_bsum[t] : 0;
    sh[t] = v;
    __syncthreads();
    for (int o = 1; o < 512; o <<= 1) {
        int x = (t >= o) ? sh[t - o] : 0;
        __syncthreads();
        sh[t] += x;
        __syncthreads();
    }
    if (t < nb) g_bsum[t] = sh[t] - v;
}
__global__ void k_scan3(int N, int E) {
    int i = blockIdx.x * blockDim.x + threadIdx.x;
    if (i < N) {
        int o = g_off[i] + g_bsum[i >> 8];
        g_off[i] = o;
        g_cur[i] = o;
    }
    if (i == 0) g_off[N] = E;
}
__global__ void k_scatter(const int* __restrict__ rows, const int* __restrict__ cols,
                          const float* __restrict__ vals, int E) {
    int e = blockIdx.x * blockDim.x + threadIdx.x;
    if (e >= E) return;
    int r = __ldg(rows + e);
    int pos = atomicAdd(&g_cur[r], 1);
    g_ccol[pos] = __ldg(cols + e);
    g_cval[pos] = __ldg(vals + e);
}

// ---------------- CSR SpMM with fused nonlinearity ---------------------------
template<int FUSE>
__global__ void k_csrmm(const float* __restrict__ T, float* __restrict__ OUT,
                        const float* __restrict__ nvec, int N) {
    int w = (blockIdx.x * blockDim.x + threadIdx.x) >> 5;
    if (w >= N) return;
    int lane = threadIdx.x & 31;
    int e0 = __ldg(g_off + w);
    int e1 = __ldg(g_off + w + 1);
    float a[4] = {0.f, 0.f, 0.f, 0.f};
    int e = e0;
    for (; e + 2 <= e1; e += 2) {
        int c0 = __ldg(g_ccol + e);
        int c1 = __ldg(g_ccol + e + 1);
        float v0 = __ldg(g_cval + e);
        float v1 = __ldg(g_cval + e + 1);
        float4 t0 = __ldg((const float4*)(T + (size_t)c0 * 128) + lane);
        float4 t1 = __ldg((const float4*)(T + (size_t)c1 * 128) + lane);
        a[0] += t0.x * v0 + t1.x * v1;
        a[1] += t0.y * v0 + t1.y * v1;
        a[2] += t0.z * v0 + t1.z * v1;
        a[3] += t0.w * v0 + t1.w * v1;
    }
    if (e < e1) {
        int c0 = __ldg(g_ccol + e);
        float v0 = __ldg(g_cval + e);
        float4 t0 = __ldg((const float4*)(T + (size_t)c0 * 128) + lane);
        a[0] += t0.x * v0; a[1] += t0.y * v0; a[2] += t0.z * v0; a[3] += t0.w * v0;
    }
    float sqrtK = g_cp[2], Kc = g_cp[1];
    if (FUSE == 1) {
        d_EL(a, sqrtK, Kc);
        float nv = __ldg(nvec + w);
        float om = 1.f - nv;
#pragma unroll
        for (int i = 0; i < 4; i++) a[i] *= om;
        d_EL(a, sqrtK, Kc);
        float b[4];
        float4 v = *((const float4*)(g_TA + (size_t)w * 128) + lane);
        b[0]=v.x*nv; b[1]=v.y*nv; b[2]=v.z*nv; b[3]=v.w*nv;
        d_EL(b, sqrtK, Kc);
#pragma unroll
        for (int i = 0; i < 4; i++) a[i] += b[i];
        d_EL(a, sqrtK, Kc);
    } else if (FUSE == 2) {
        d_EL(a, sqrtK, Kc);
    }
    *((float4*)(OUT + (size_t)w * 128) + lane) = make_float4(a[0], a[1], a[2], a[3]);
}

// H rows b*51+l = relu(P[b*50+l]); H row b*51+50 = relu(sum_l P[b*50+l])
__global__ void k_hsum(int B, int L) {
    int b = blockIdx.x;
    int j = threadIdx.x;            // 64 threads
    const float* Pb = g_P + (size_t)b * L * 64;
    float* Hb = g_H + (size_t)b * (L + 1) * 64;
    float s = 0.f;
    for (int l = 0; l < L; l++) {
        float p = Pb[(size_t)l * 64 + j];
        s += p;
        Hb[(size_t)l * 64 + j] = fmaxf(p, 0.f);
    }
    Hb[(size_t)L * 64 + j] = fmaxf(s, 0.f);
}

__global__ void k_addbias(float* __restrict__ o, const float* __restrict__ bias, int n) {
    int i = blockIdx.x * blockDim.x + threadIdx.x;
    if (i < n) o[i] += __ldg(bias + (i & 127));
}

__global__ void k_loss(const float* __restrict__ sel, const float* __restrict__ cls,
                       const float* __restrict__ cb, const int* __restrict__ lab, int B) {
    int b = (blockIdx.x * blockDim.x + threadIdx.x) >> 5;
    if (b >= B) return;
    int lane = threadIdx.x & 31;
    const float* row = sel + (size_t)b * 128;
    float d0 = 0.f, d1 = 0.f;
#pragma unroll
    for (int i = 0; i < 4; i++) {
        int d = lane * 4 + i;
        float o = row[d];
        d0 += o * __ldg(cls + d * 2 + 0);
        d1 += o * __ldg(cls + d * 2 + 1);
    }
    d0 = wsum(d0); d1 = wsum(d1);
    if (lane == 0) {
        float p0 = d0 + __ldg(cb + 0);
        float p1 = d1 + __ldg(cb + 1);
        float m = fmaxf(p0, p1);
        float lse = m + logf(expf(p0 - m) + expf(p1 - m));
        int y = __ldg(lab + b);
        float lp = (y == 0 ? p0 : p1) - lse;
        atomicAdd(&g_loss, lp);
    }
}

__global__ void k_final(float* __restrict__ out, int out_size, int B) {
    out[0] = -g_loss / (float)B;
    out[out_size - 1] = g_cp[0];
}

// ---------------- mma.sync helpers ----------------
__device__ __forceinline__ void ldm_x4(uint32_t* r, uint32_t addr) {
    asm volatile("ldmatrix.sync.aligned.m8n8.x4.shared.b16 {%0,%1,%2,%3}, [%4];"
        : "=r"(r[0]), "=r"(r[1]), "=r"(r[2]), "=r"(r[3]) : "r"(addr));
}
__device__ __forceinline__ void mma_bf16(float* c, const uint32_t* a, const uint32_t* b) {
    asm volatile("mma.sync.aligned.m16n8k16.row.col.f32.bf16.bf16.f32 "
        "{%0,%1,%2,%3}, {%4,%5,%6,%7}, {%8,%9}, {%0,%1,%2,%3};"
        : "+f"(c[0]), "+f"(c[1]), "+f"(c[2]), "+f"(c[3])
        : "r"(a[0]), "r"(a[1]), "r"(a[2]), "r"(a[3]), "r"(b[0]), "r"(b[1]));
}
__device__ __forceinline__ uint32_t pack_hi2(float x, float y) {
    __nv_bfloat16 hx = __float2bfloat16(x), hy = __float2bfloat16(y);
    return ((uint32_t)__bfloat16_as_ushort(hy) << 16) | __bfloat16_as_ushort(hx);
}
__device__ __forceinline__ uint32_t pack_lo2(float x, float y) {
    __nv_bfloat16 hx = __float2bfloat16(x), hy = __float2bfloat16(y);
    __nv_bfloat16 lx = __float2bfloat16(x - __bfloat162float(hx));
    __nv_bfloat16 ly = __float2bfloat16(y - __bfloat162float(hy));
    return ((uint32_t)__bfloat16_as_ushort(ly) << 16) | __bfloat16_as_ushort(lx);
}
__device__ __forceinline__ void packhl(float x, float y, uint32_t& hi, uint32_t& lo) {
    __nv_bfloat16 hx = __float2bfloat16(x), hy = __float2bfloat16(y);
    hi = ((uint32_t)__bfloat16_as_ushort(hy) << 16) | __bfloat16_as_ushort(hx);
    __nv_bfloat16 lx = __float2bfloat16(x - __bfloat162float(hx));
    __nv_bfloat16 ly = __float2bfloat16(y - __bfloat162float(hy));
    lo = ((uint32_t)__bfloat16_as_ushort(ly) << 16) | __bfloat16_as_ushort(lx);
}
__device__ __forceinline__ void cp16(uint32_t dst, const void* src, bool valid) {
    int sz = valid ? 16 : 0;
    asm volatile("cp.async.cg.shared.global [%0], [%1], 16, %2;"
                 :: "r"(dst), "l"(src), "r"(sz) : "memory");
}
#define CP_COMMIT() asm volatile("cp.async.commit_group;" ::: "memory")
#define CP_WAIT(n)  asm volatile("cp.async.wait_group %0;" :: "n"(n) : "memory")

// ---------------- cp.async-pipelined GEMM (K=128, BM=BN=128, 512 thr) --------
#define PLALD 36
#define PLBLD 132
#define PLASTG (128 * PLALD)
#define PLBSTG (32 * PLBLD)
#define PL_SMEM ((4 * PLASTG + 4 * PLBSTG) * 4)
template<int NPASS, bool ASCALE>
__global__ void __launch_bounds__(512)
mmgemm_pl(int M, const float* __restrict__ A, const float* __restrict__ scale,
          const float* __restrict__ B0, const float* __restrict__ B1,
          float* __restrict__ C0, float* __restrict__ C1) {
    extern __shared__ __align__(16) float psm[];
    float* Asm = psm;
    float* Bsm = psm + 4 * PLASTG;

    int tid = threadIdx.x, lane = tid & 31, wid = tid >> 5;
    int wm = wid >> 2, wn = wid & 3;
    int m0 = blockIdx.x * 128;
    uint32_t sbase = (uint32_t)__cvta_generic_to_shared(psm);

    float sc[2][2];
    if (ASCALE) {
#pragma unroll
        for (int mt = 0; mt < 2; mt++) {
            int r0 = m0 + wm * 32 + mt * 16 + (lane >> 2);
            sc[mt][0] = (r0 < M) ? __ldg(scale + r0) : 0.f;
            sc[mt][1] = (r0 + 8 < M) ? __ldg(scale + r0 + 8) : 0.f;
        }
    }

    auto issueA = [&](int t) {
#pragma unroll
        for (int cc = 0; cc < 2; cc++) {
            int c = tid + cc * 512;
            int row = c >> 3, q = c & 7;
            uint32_t dst = sbase + (uint32_t)((t * PLASTG + row * PLALD + q * 4) * 4);
            const float* src = A + (size_t)(m0 + row) * 128 + t * 32 + q * 4;
            cp16(dst, src, (m0 + row) < M);
        }
    };
    auto issueB = [&](const float* Bg, int t) {
#pragma unroll
        for (int cc = 0; cc < 2; cc++) {
            int c = tid + cc * 512;
            int kr = c >> 5, q = c & 31;
            uint32_t dst = sbase + (uint32_t)((4 * PLASTG + t * PLBSTG + kr * PLBLD + q * 4) * 4);
            const float* src = Bg + (size_t)(t * 32 + kr) * 128 + q * 4;
            cp16(dst, src, true);
        }
    };

#pragma unroll
    for (int t = 0; t < 4; t++) { issueA(t); issueB(B0, t); CP_COMMIT(); }

    float acc[2][4][4];
    int kbl = (lane & 3) * 2;
    int rlo = lane >> 2;

#pragma unroll
    for (int pass = 0; pass < NPASS; pass++) {
#pragma unroll
        for (int i = 0; i < 2; i++)
#pragma unroll
            for (int j = 0; j < 4; j++)
#pragma unroll
                for (int q = 0; q < 4; q++) acc[i][j][q] = 0.f;

#pragma unroll
        for (int t = 0; t < 4; t++) {
            if (t == 0) CP_WAIT(3);
            else if (t == 1) CP_WAIT(2);
            else if (t == 2) CP_WAIT(1);
            else CP_WAIT(0);
            __syncthreads();
            const float* At = Asm + t * PLASTG;
            const float* Bt = Bsm + t * PLBSTG;
#pragma unroll
            for (int kk = 0; kk < 32; kk += 16) {
                int kb = kk + kbl;
                uint32_t ah[2][4], al[2][4], bh[2][4], bl[2][4];
#pragma unroll
                for (int mt = 0; mt < 2; mt++) {
                    const float* pr0 = At + (wm * 32 + mt * 16 + rlo) * PLALD;
                    const float* pr1 = pr0 + 8 * PLALD;
                    float f00 = pr0[kb], f01 = pr0[kb+1], f08 = pr0[kb+8], f09 = pr0[kb+9];
                    float f10 = pr1[kb], f11 = pr1[kb+1], f18 = pr1[kb+8], f19 = pr1[kb+9];
                    if (ASCALE) {
                        float s0 = sc[mt][0], s1 = sc[mt][1];
                        f00 *= s0; f01 *= s0; f08 *= s0; f09 *= s0;
                        f10 *= s1; f11 *= s1; f18 *= s1; f19 *= s1;
                        if (t == 0 && kb == 0) { f00 = 0.f; f10 = 0.f; }
                    }
                    packhl(f00, f01, ah[mt][0], al[mt][0]);
                    packhl(f10, f11, ah[mt][1], al[mt][1]);
                    packhl(f08, f09, ah[mt][2], al[mt][2]);
                    packhl(f18, f19, ah[mt][3], al[mt][3]);
                }
#pragma unroll
                for (int np = 0; np < 2; np++) {
#pragma unroll
                    for (int h = 0; h < 2; h++) {
                        int nB = wn * 32 + np * 16 + h * 8 + rlo;
                        float g0 = Bt[(kb)     * PLBLD + nB];
                        float g1 = Bt[(kb + 1) * PLBLD + nB];
                        float g8 = Bt[(kb + 8) * PLBLD + nB];
                        float g9 = Bt[(kb + 9) * PLBLD + nB];
                        packhl(g0, g1, bh[np][h*2+0], bl[np][h*2+0]);
                        packhl(g8, g9, bh[np][h*2+1], bl[np][h*2+1]);
                    }
                }
#pragma unroll
                for (int np = 0; np < 2; np++)
#pragma unroll
                    for (int mt = 0; mt < 2; mt++) {
                        mma_bf16(acc[mt][2*np],   ah[mt], bh[np]);
                        mma_bf16(acc[mt][2*np+1], ah[mt], bh[np] + 2);
                    }
#pragma unroll
                for (int np = 0; np < 2; np++)
#pragma unroll
                    for (int mt = 0; mt < 2; mt++) {
                        mma_bf16(acc[mt][2*np],   ah[mt], bl[np]);
                        mma_bf16(acc[mt][2*np+1], ah[mt], bl[np] + 2);
                    }
#pragma unroll
                for (int np = 0; np < 2; np++)
#pragma unroll
                    for (int mt = 0; mt < 2; mt++) {
                        mma_bf16(acc[mt][2*np],   al[mt], bh[np]);
                        mma_bf16(acc[mt][2*np+1], al[mt], bh[np] + 2);
                    }
            }
        }

        float* Cg = pass ? C1 : C0;
#pragma unroll
        for (int mt = 0; mt < 2; mt++) {
            int row0 = m0 + wm * 32 + mt * 16 + rlo;
            int row1 = row0 + 8;
#pragma unroll
            for (int nt = 0; nt < 4; nt++) {
                int col = wn * 32 + nt * 8 + (lane & 3) * 2;
                if (row0 < M)
                    *reinterpret_cast<float2*>(Cg + (size_t)row0 * 128 + col) =
                        make_float2(acc[mt][nt][0], acc[mt][nt][1]);
                if (row1 < M)
                    *reinterpret_cast<float2*>(Cg + (size_t)row1 * 128 + col) =
                        make_float2(acc[mt][nt][2], acc[mt][nt][3]);
            }
        }
        if (pass + 1 < NPASS) {
            __syncthreads();
#pragma unroll
            for (int t = 0; t < 4; t++) { issueB(B1, t); CP_COMMIT(); }
        }
    }
}

// ---------------- general mma.sync GEMM (register-prefetch; readout path) ----
template<int BM, int BN, int BK, int NWM, int NWN, bool BT, bool RELU, bool ASCALE,
         bool ATOMIC, bool GATHER>
__global__ void __launch_bounds__(NWM * NWN * 32)
mmgemm(int M, int N, int K, int kChunk,
       const float* __restrict__ A, int lda,
       const float* __restrict__ B, int ldb,
       float* __restrict__ C, int ldc,
       const float* __restrict__ scale, const int* __restrict__ gidx) {
    constexpr int THREADS = NWM * NWN * 32;
    constexpr int WM = BM / NWM;
    constexpr int WN = BN / NWN;
    constexpr int MT = WM / 16;
    constexpr int NT = WN / 8;
    constexpr int NP = NT / 2;
    constexpr int LDK = BK + 8;
    constexpr int NA = (BM * (BK / 4) + THREADS - 1) / THREADS;
    constexpr int NBCNT = BT ? BN * (BK / 4) : BK * (BN / 4);
    constexpr int NB = (NBCNT + THREADS - 1) / THREADS;

    __shared__ __align__(16) __nv_bfloat16 AsH[BM * LDK];
    __shared__ __align__(16) __nv_bfloat16 AsL[BM * LDK];
    __shared__ __align__(16) __nv_bfloat16 BsH[BN * LDK];
    __shared__ __align__(16) __nv_bfloat16 BsL[BN * LDK];

    int tid = threadIdx.x;
    int lane = tid & 31;
    int wid = tid >> 5;
    int wm = wid / NWN;
    int wn = wid % NWN;
    int m0 = blockIdx.x * BM;
    int n0 = blockIdx.y * BN;
    int kStart = blockIdx.z * kChunk;
    int kEnd = min(K, kStart + kChunk);

    float acc[MT][NT][4];
#pragma unroll
    for (int i = 0; i < MT; i++)
#pragma unroll
        for (int j = 0; j < NT; j++)
#pragma unroll
            for (int q = 0; q < 4; q++) acc[i][j][q] = 0.f;

    float4 pa[NA]; float ps[NA]; float4 pb[NB];

    auto loadA = [&](int k0) {
#pragma unroll
        for (int t = 0; t < NA; t++) {
            int i = tid + t * THREADS;
            float4 v = make_float4(0.f, 0.f, 0.f, 0.f);
            float s = 0.f;
            if (i < BM * (BK / 4)) {
                int r = i / (BK / 4);
                int kc = (i % (BK / 4)) * 4;
                int gr = m0 + r;
                if (gr < M) {
                    size_t ar = GATHER ? (size_t)__ldg(gidx + gr) : (size_t)gr;
                    v = *reinterpret_cast<const float4*>(A + ar * lda + k0 + kc);
                    if (ASCALE) s = __ldg(scale + gr);
                }
            }
            pa[t] = v;
            if (ASCALE) ps[t] = s;
        }
    };
    auto storeA = [&](int k0) {
#pragma unroll
        for (int t = 0; t < NA; t++) {
            int i = tid + t * THREADS;
            if (i < BM * (BK / 4)) {
                int r = i / (BK / 4);
                int kc = (i % (BK / 4)) * 4;
                float4 v = pa[t];
                if (ASCALE) {
                    float s = ps[t];
                    v.x *= s; v.y *= s; v.z *= s; v.w *= s;
                    if (k0 + kc == 0) v.x = 0.f;
                }
                *(uint32_t*)&AsH[r * LDK + kc]     = pack_hi2(v.x, v.y);
                *(uint32_t*)&AsH[r * LDK + kc + 2] = pack_hi2(v.z, v.w);
                *(uint32_t*)&AsL[r * LDK + kc]     = pack_lo2(v.x, v.y);
                *(uint32_t*)&AsL[r * LDK + kc + 2] = pack_lo2(v.z, v.w);
            }
        }
    };
    auto loadB = [&](int k0) {
#pragma unroll
        for (int t = 0; t < NB; t++) {
            int i = tid + t * THREADS;
            float4 v = make_float4(0.f, 0.f, 0.f, 0.f);
            if (i < NBCNT) {
                if (BT) {
                    int r = i / (BK / 4);
                    int kc = (i % (BK / 4)) * 4;
                    v = *reinterpret_cast<const float4*>(B + (size_t)(n0 + r) * ldb + k0 + kc);
                } else {
                    int kk = i / (BN / 4);
                    int nc = (i % (BN / 4)) * 4;
                    v = *reinterpret_cast<const float4*>(B + (size_t)(k0 + kk) * ldb + n0 + nc);
                }
            }
            pb[t] = v;
        }
    };
    auto storeB = [&]() {
#pragma unroll
        for (int t = 0; t < NB; t++) {
            int i = tid + t * THREADS;
            if (i < NBCNT) {
                float4 v = pb[t];
                if (BT) {
                    int r = i / (BK / 4);
                    int kc = (i % (BK / 4)) * 4;
                    *(uint32_t*)&BsH[r * LDK + kc]     = pack_hi2(v.x, v.y);
                    *(uint32_t*)&BsH[r * LDK + kc + 2] = pack_hi2(v.z, v.w);
                    *(uint32_t*)&BsL[r * LDK + kc]     = pack_lo2(v.x, v.y);
                    *(uint32_t*)&BsL[r * LDK + kc + 2] = pack_lo2(v.z, v.w);
                } else {
                    int kk = i / (BN / 4);
                    int nc = (i % (BN / 4)) * 4;
                    float vv[4] = {v.x, v.y, v.z, v.w};
#pragma unroll
                    for (int j = 0; j < 4; j++) {
                        __nv_bfloat16 h = __float2bfloat16(vv[j]);
                        BsH[(nc + j) * LDK + kk] = h;
                        BsL[(nc + j) * LDK + kk] = __float2bfloat16(vv[j] - __bfloat162float(h));
                    }
                }
            }
        }
    };

    int a_row = (lane & 7) + ((lane >> 3) & 1) * 8;
    int a_kof = (lane >> 4) * 8;
    int b_row = (lane & 7) + (lane >> 4) * 8;
    int b_kof = ((lane >> 3) & 1) * 8;

    loadA(kStart);
    loadB(kStart);

    for (int k0 = kStart; k0 < kEnd; k0 += BK) {
        storeA(k0);
        storeB();
        __syncthreads();
        if (k0 + BK < kEnd) {
            loadA(k0 + BK);
            loadB(k0 + BK);
        }
#pragma unroll
        for (int kk = 0; kk < BK; kk += 16) {
            uint32_t ah[MT][4], al[MT][4], bh[NP][4], bl[NP][4];
#pragma unroll
            for (int mt = 0; mt < MT; mt++) {
                int row = wm * WM + mt * 16 + a_row;
                int col = kk + a_kof;
                ldm_x4(ah[mt], (uint32_t)__cvta_generic_to_shared(&AsH[row * LDK + col]));
                ldm_x4(al[mt], (uint32_t)__cvta_generic_to_shared(&AsL[row * LDK + col]));
            }
#pragma unroll
            for (int np = 0; np < NP; np++) {
                int nrow = wn * WN + np * 16 + b_row;
                int col = kk + b_kof;
                ldm_x4(bh[np], (uint32_t)__cvta_generic_to_shared(&BsH[nrow * LDK + col]));
                ldm_x4(bl[np], (uint32_t)__cvta_generic_to_shared(&BsL[nrow * LDK + col]));
            }
#pragma unroll
            for (int np = 0; np < NP; np++)
#pragma unroll
                for (int mt = 0; mt < MT; mt++) {
                    mma_bf16(acc[mt][2*np],   ah[mt], bh[np]);
                    mma_bf16(acc[mt][2*np+1], ah[mt], bh[np] + 2);
                }
#pragma unroll
            for (int np = 0; np < NP; np++)
#pragma unroll
                for (int mt = 0; mt < MT; mt++) {
                    mma_bf16(acc[mt][2*np],   ah[mt], bl[np]);
                    mma_bf16(acc[mt][2*np+1], ah[mt], bl[np] + 2);
                }
#pragma unroll
            for (int np = 0; np < NP; np++)
#pragma unroll
                for (int mt = 0; mt < MT; mt++) {
                    mma_bf16(acc[mt][2*np],   al[mt], bh[np]);
                    mma_bf16(acc[mt][2*np+1], al[mt], bh[np] + 2);
                }
        }
        __syncthreads();
    }

#pragma unroll
    for (int mt = 0; mt < MT; mt++) {
        int row0 = m0 + wm * WM + mt * 16 + (lane >> 2);
        int row1 = row0 + 8;
#pragma unroll
        for (int nt = 0; nt < NT; nt++) {
            int col = n0 + wn * WN + nt * 8 + (lane & 3) * 2;
            float c0 = acc[mt][nt][0], c1 = acc[mt][nt][1];
            float c2 = acc[mt][nt][2], c3 = acc[mt][nt][3];
            if (RELU) {
                c0 = fmaxf(c0, 0.f); c1 = fmaxf(c1, 0.f);
                c2 = fmaxf(c2, 0.f); c3 = fmaxf(c3, 0.f);
            }
            if (ATOMIC) {
                if (row0 < M) {
                    atomicAdd(C + (size_t)row0 * ldc + col,     c0);
                    atomicAdd(C + (size_t)row0 * ldc + col + 1, c1);
                }
                if (row1 < M) {
                    atomicAdd(C + (size_t)row1 * ldc + col,     c2);
                    atomicAdd(C + (size_t)row1 * ldc + col + 1, c3);
                }
            } else {
                if (row0 < M)
                    *reinterpret_cast<float2*>(C + (size_t)row0 * ldc + col) = make_float2(c0, c1);
                if (row1 < M)
                    *reinterpret_cast<float2*>(C + (size_t)row1 * ldc + col) = make_float2(c2, c3);
            }
        }
    }
}

// ---------------- host ----------------
extern "C" void kernel_launch(void* const* d_in, const int* in_sizes, int n_in,
                              void* d_out, int out_size) {
    const float* A1    = (const float*)d_in[0];
    const int*   rows  = (const int*)  d_in[1];
    const int*   cols  = (const int*)  d_in[2];
    const float* vals  = (const float*)d_in[3];
    const int*   bidx  = (const int*)  d_in[4];
    const int*   blab  = (const int*)  d_in[5];
    const float* rawc  = (const float*)d_in[6];
    const float* nvec  = (const float*)d_in[7];
    const float* Lin1  = (const float*)d_in[8];
    const float* Lin1b = (const float*)d_in[9];
    const float* gc1w  = (const float*)d_in[10];
    const float* gc1b  = (const float*)d_in[11];
    const float* gc2w  = (const float*)d_in[12];
    const float* gc2b  = (const float*)d_in[13];
    const float* wgt   = (const float*)d_in[14];
    const float* lin1w = (const float*)d_in[15];
    const float* lin1b = (const float*)d_in[16];
    const float* cls   = (const float*)d_in[17];
    const float* clsb  = (const float*)d_in[18];
    float* out = (float*)d_out;

    int N = in_sizes[0] / 128;
    int E = in_sizes[1];
    int B = in_sizes[5];
    int L = in_sizes[4] / B;

    float *pScale, *pU1, *pU2, *pTA, *pT1, *pTM, *pT2, *pX2, *pP, *pH;
    cudaGetSymbolAddress((void**)&pScale, g_scale);
    cudaGetSymbolAddress((void**)&pU1, g_U1);
    cudaGetSymbolAddress((void**)&pU2, g_U2);
    cudaGetSymbolAddress((void**)&pTA, g_TA);
    cudaGetSymbolAddress((void**)&pT1, g_T1);
    cudaGetSymbolAddress((void**)&pTM, g_TM);
    cudaGetSymbolAddress((void**)&pT2, g_T2);
    cudaGetSymbolAddress((void**)&pX2, g_X2);
    cudaGetSymbolAddress((void**)&pP,  g_P);
    cudaGetSymbolAddress((void**)&pH,  g_H);

    cudaFuncSetAttribute(mmgemm_pl<2, true>,
                         cudaFuncAttributeMaxDynamicSharedMemorySize, PL_SMEM);
    cudaFuncSetAttribute(mmgemm_pl<1, false>,
                         cudaFuncAttributeMaxDynamicSharedMemorySize, PL_SMEM);

    int nwBlocks = (N + 7) / 8;
    int gG = (N + 127) / 128;
    int nb = (N + 255) / 256;

    // Fork a side stream (capturable fork/join): CSR build + out-zero run
    // concurrently with the scale/GEMM/l1nl front half. Stream+events are
    // created per call (host-side only; graph replays carry just the nodes).
    cudaStream_t s2;
    cudaStreamCreateWithFlags(&s2, cudaStreamNonBlocking);
    cudaEvent_t evFork, evJoin;
    cudaEventCreateWithFlags(&evFork, cudaEventDisableTiming);
    cudaEventCreateWithFlags(&evJoin, cudaEventDisableTiming);

    cudaEventRecord(evFork, 0);
    cudaStreamWaitEvent(s2, evFork, 0);
    // ---- side branch: CSR build (independent of c / scale / GEMMs)
    k_zcnt<<<(N + 255) / 256, 256, 0, s2>>>(N);
    k_hist<<<(E + 255) / 256, 256, 0, s2>>>(rows, E);
    k_scan1<<<nb, 256, 0, s2>>>(N);
    k_scan2<<<1, 512, 0, s2>>>(nb);
    k_scan3<<<(N + 255) / 256, 256, 0, s2>>>(N, E);
    k_scatter<<<(E + 255) / 256, 256, 0, s2>>>(rows, cols, vals, E);
    k_zero<<<1024, 256, 0, s2>>>(out, out_size);
    cudaEventRecord(evJoin, s2);

    // ---- main branch
    k_init<<<1, 32>>>(rawc, Lin1b, gc1b, gc2b);
    k_scale<<<nwBlocks, 256>>>(A1, N);
    // U1 = T0 @ Lin1 ; U2 = T0 @ gc1_w — cp.async-pipelined dual GEMM
    mmgemm_pl<2, true><<<gG, 512, PL_SMEM>>>(N, A1, pScale, Lin1, gc1w, pU1, pU2);
    // nonlinear: t_a1 (Lin1 path) and T1 (gc1 path)
    k_l1nl<<<nwBlocks, 256>>>(N);

    // join: SpMM needs the CSR
    cudaStreamWaitEvent(0, evJoin, 0);

    // SpMM #1 with fused mix -> TM
    k_csrmm<1><<<nwBlocks, 256>>>(pT1, pTM, nvec, N);
    // U3 = Tm @ gc2_w (into g_U1) — pipelined
    mmgemm_pl<1, false><<<gG, 512, PL_SMEM>>>(N, pTM, nullptr, gc2w, nullptr, pU1, nullptr);
    k_l2nl<<<nwBlocks, 256>>>(N);
    // SpMM #2 with fused EL -> X2
    k_csrmm<2><<<nwBlocks, 256>>>(pT2, pX2, nullptr, N);
    // readout: P = X2[bidx] @ wgt  (gather fused into GEMM A-load)
    int MP = B * L;
    mmgemm<128,64,32,4,2,false,false,false,false,true><<<dim3((MP + 127) / 128, 1, 1), 256>>>(
        MP, 64, 128, 128, pX2, 128, wgt, 64, pP, 64, nullptr, bidx);
    // H rows + appended sum row (relu applied here)
    k_hsum<<<B, 64>>>(B, L);
    // OUT = H @ lin1_w^T, split-K (8) atomic into d_out+1
    int KD = (L + 1) * 64;
    int kChunk = 416;
    int zs = (KD + kChunk - 1) / kChunk;
    mmgemm<128,128,32,4,4,true,false,false,true,false><<<dim3((B + 127) / 128, 1, zs), 512>>>(
        B, 128, KD, kChunk, pH, KD, lin1w, KD, out + 1, 128, nullptr, nullptr);
    k_addbias<<<(B * 128 + 255) / 256, 256>>>(out + 1, lin1b, B * 128);
    // loss + finalize
    k_loss<<<(B + 7) / 8, 256>>>(out + 1, cls, clsb, blab, B);
    k_final<<<1, 1>>>(out, out_size, B);
}